// round 4
// baseline (speedup 1.0000x reference)
#include <cuda_runtime.h>
#include <math.h>

#define NN   50000
#define EE   800000
#define ETOT 850000
#define FIN  256
#define HCC  512      // H*C
#define NH   8
#define CHN  64
#define NOUT 40
#define H2S  64       // padded stride for layer-2 features

// ---------------- scratch (device globals; no allocation allowed) ----------
__device__ __align__(16) float g_h1[(size_t)NN * HCC];    // layer1 linear output
__device__ __align__(16) float g_agg1[(size_t)NN * HCC];  // layer1 GAT out (relu+bias)
__device__ __align__(16) float g_h2[(size_t)NN * H2S];    // layer2 linear (padded 64)
__device__ __align__(16) float g_W2p[HCC * H2S];
__device__ float g_as1[NN * NH];
__device__ float g_ad1[NN * NH];
__device__ float g_as2[NN];
__device__ float g_ad2[NN];
__device__ int   g_cnt[NN];
__device__ int   g_rowstart[NN];
__device__ int   g_cursor[NN];
__device__ int   g_esrc[ETOT];
__device__ int   g_e64;   // 1 if edge_index is int64, 0 if int32

// ---------------- edge dtype sniffing ----------------
// int64 values < 2^31 have zero odd 32-bit words; int32 edge ids are random.
__global__ void k_detect(const int* __restrict__ ei32) {
    int any = 0;
#pragma unroll
    for (int i = 1; i < 256; i += 2) any |= ei32[i];
    g_e64 = (any == 0) ? 1 : 0;
}

// ---------------- small utility kernels ----------------
__global__ void k_zero_cnt() {
    int i = blockIdx.x * blockDim.x + threadIdx.x;
    if (i < NN) g_cnt[i] = 0;
}

__global__ void k_w2pad(const float* __restrict__ W2) {
    int idx = blockIdx.x * blockDim.x + threadIdx.x;
    if (idx >= HCC * H2S) return;
    int r = idx >> 6, c = idx & 63;
    g_W2p[idx] = (c < NOUT) ? W2[r * NOUT + c] : 0.f;
}

// ---------------- fp32 tiled SGEMM body: C[M,N] = A[M,K] @ B[K,N] ----------
// BM=128 BN=64 BK=16, 256 threads, 8x4 per-thread tile. K%16==0, N%64==0.
__device__ __forceinline__ void sgemm_body(const float* __restrict__ A,
                                           const float* __restrict__ B,
                                           float* __restrict__ C,
                                           int M, int K, int Ncols) {
    const int BM = 128, BN = 64, BK = 16, TM = 8, TN = 4;
    __shared__ __align__(16) float As[BK][BM];
    __shared__ __align__(16) float Bs[BK][BN];
    int tid = threadIdx.x;
    int rowBase = blockIdx.y * BM;
    int colBase = blockIdx.x * BN;
    int ty = tid / (BN / TN);      // 0..15
    int tx = tid % (BN / TN);      // 0..15

    float acc[TM][TN];
#pragma unroll
    for (int i = 0; i < TM; i++)
#pragma unroll
        for (int j = 0; j < TN; j++) acc[i][j] = 0.f;

    for (int kt = 0; kt < K; kt += BK) {
        // load A tile (128x16) = 512 float4, 2 per thread; store transposed
#pragma unroll
        for (int it = 0; it < 2; it++) {
            int f = tid + it * 256;
            int r = f >> 2;
            int k4 = f & 3;
            float4 v = make_float4(0.f, 0.f, 0.f, 0.f);
            int gr = rowBase + r;
            if (gr < M)
                v = *(const float4*)&A[(size_t)gr * K + kt + k4 * 4];
            As[k4 * 4 + 0][r] = v.x;
            As[k4 * 4 + 1][r] = v.y;
            As[k4 * 4 + 2][r] = v.z;
            As[k4 * 4 + 3][r] = v.w;
        }
        // load B tile (16x64) = 256 float4, 1 per thread
        {
            int r = tid >> 4;
            int c4 = tid & 15;
            *(float4*)&Bs[r][c4 * 4] =
                *(const float4*)&B[(size_t)(kt + r) * Ncols + colBase + c4 * 4];
        }
        __syncthreads();
#pragma unroll
        for (int k = 0; k < BK; k++) {
            float ra[TM], rb[TN];
            float4 a0 = *(float4*)&As[k][ty * TM];
            float4 a1 = *(float4*)&As[k][ty * TM + 4];
            ra[0] = a0.x; ra[1] = a0.y; ra[2] = a0.z; ra[3] = a0.w;
            ra[4] = a1.x; ra[5] = a1.y; ra[6] = a1.z; ra[7] = a1.w;
            float4 b0 = *(float4*)&Bs[k][tx * TN];
            rb[0] = b0.x; rb[1] = b0.y; rb[2] = b0.z; rb[3] = b0.w;
#pragma unroll
            for (int i = 0; i < TM; i++)
#pragma unroll
                for (int j = 0; j < TN; j++) acc[i][j] += ra[i] * rb[j];
        }
        __syncthreads();
    }
#pragma unroll
    for (int i = 0; i < TM; i++) {
        int gr = rowBase + ty * TM + i;
        if (gr < M) {
            float4 o = make_float4(acc[i][0], acc[i][1], acc[i][2], acc[i][3]);
            *(float4*)&C[(size_t)gr * Ncols + colBase + tx * TN] = o;
        }
    }
}

__global__ void __launch_bounds__(256)
k_sgemm1(const float* __restrict__ A, const float* __restrict__ B) {
    sgemm_body(A, B, g_h1, NN, FIN, HCC);
}

__global__ void __launch_bounds__(256)
k_sgemm2() {
    sgemm_body(g_agg1, g_W2p, g_h2, NN, HCC, H2S);
}

// ---------------- layer1 attention coefficients ----------------
// grid = NN blocks, 256 threads (8 warps = 8 heads)
__global__ void k_alpha1(const float* __restrict__ a_src,
                         const float* __restrict__ a_dst) {
    int n = blockIdx.x;
    int h = threadIdx.x >> 5;
    int lane = threadIdx.x & 31;
    size_t base = (size_t)n * HCC + h * CHN;
    float v0 = g_h1[base + lane];
    float v1 = g_h1[base + 32 + lane];
    float s = v0 * a_src[h * CHN + lane] + v1 * a_src[h * CHN + 32 + lane];
    float d = v0 * a_dst[h * CHN + lane] + v1 * a_dst[h * CHN + 32 + lane];
#pragma unroll
    for (int off = 16; off > 0; off >>= 1) {
        s += __shfl_xor_sync(0xffffffffu, s, off);
        d += __shfl_xor_sync(0xffffffffu, d, off);
    }
    if (lane == 0) {
        g_as1[n * NH + h] = s;
        g_ad1[n * NH + h] = d;
    }
}

// ---------------- CSR build ----------------
__device__ __forceinline__ int edge_val(const int* __restrict__ ei32, int idx, int e64) {
    return e64 ? ei32[2 * (size_t)idx] : ei32[idx];
}

__global__ void k_hist(const int* __restrict__ ei32) {
    int e = blockIdx.x * blockDim.x + threadIdx.x;
    if (e >= ETOT) return;
    int e64 = g_e64;
    int dst = (e < EE) ? edge_val(ei32, EE + e, e64) : (e - EE);
    atomicAdd(&g_cnt[dst], 1);
}

__global__ void k_scan() {
    __shared__ int sh[1024];
    int t = threadIdx.x;
    const int CHUNK = 49;  // 1024*49 = 50176 >= 50000
    int lo = t * CHUNK;
    int hi = lo + CHUNK; if (hi > NN) hi = NN;
    int s = 0;
    for (int i = lo; i < hi; i++) s += g_cnt[i];
    sh[t] = s;
    __syncthreads();
    for (int off = 1; off < 1024; off <<= 1) {
        int v = (t >= off) ? sh[t - off] : 0;
        __syncthreads();
        sh[t] += v;
        __syncthreads();
    }
    int run = (t == 0) ? 0 : sh[t - 1];
    for (int i = lo; i < hi; i++) {
        g_rowstart[i] = run;
        g_cursor[i] = run;
        run += g_cnt[i];
    }
}

__global__ void k_scatter(const int* __restrict__ ei32) {
    int e = blockIdx.x * blockDim.x + threadIdx.x;
    if (e >= ETOT) return;
    int e64 = g_e64;
    int src, dst;
    if (e < EE) {
        src = edge_val(ei32, e, e64);
        dst = edge_val(ei32, EE + e, e64);
    } else {
        src = e - EE; dst = e - EE;
    }
    int p = atomicAdd(&g_cursor[dst], 1);
    g_esrc[p] = src;
}

// ---------------- layer1 aggregate: warp per dst node ----------------
// out[dst] = relu( sum_e softmax(e)*h1[src] + b1 )
// (max-shift skipped: logits are O(1), exp never overflows; math identical)
__global__ void k_agg1(const float* __restrict__ b1) {
    int warp = (blockIdx.x * blockDim.x + threadIdx.x) >> 5;
    int lane = threadIdx.x & 31;
    if (warp >= NN) return;
    int n = warp;
    float adv = 0.f;
    if (lane < NH) adv = g_ad1[n * NH + lane];
    float ssum = 0.f;
    float4 acc[4];
#pragma unroll
    for (int c = 0; c < 4; c++) acc[c] = make_float4(0.f, 0.f, 0.f, 0.f);

    int start = g_rowstart[n];
    int cnt = g_cnt[n];
    int hsel = lane >> 4;  // which half of the head-pair this lane's columns hit
    for (int i = 0; i < cnt; i++) {
        int s = g_esrc[start + i];
        float wv = 0.f;
        if (lane < NH) {
            float e = g_as1[s * NH + lane] + adv;
            e = (e > 0.f) ? e : 0.2f * e;
            wv = expf(e);
            ssum += wv;
        }
        const float4* hp = (const float4*)&g_h1[(size_t)s * HCC];
#pragma unroll
        for (int c = 0; c < 4; c++) {
            float w = __shfl_sync(0xffffffffu, wv, 2 * c + hsel);
            float4 hv = hp[c * 32 + lane];
            acc[c].x += w * hv.x;
            acc[c].y += w * hv.y;
            acc[c].z += w * hv.z;
            acc[c].w += w * hv.w;
        }
    }
    float4* op = (float4*)&g_agg1[(size_t)n * HCC];
#pragma unroll
    for (int c = 0; c < 4; c++) {
        float sden = __shfl_sync(0xffffffffu, ssum, 2 * c + hsel);
        float inv = 1.f / sden;
        float4 bv = *(const float4*)&b1[c * 128 + lane * 4];
        float4 o;
        o.x = fmaxf(acc[c].x * inv + bv.x, 0.f);
        o.y = fmaxf(acc[c].y * inv + bv.y, 0.f);
        o.z = fmaxf(acc[c].z * inv + bv.z, 0.f);
        o.w = fmaxf(acc[c].w * inv + bv.w, 0.f);
        op[c * 32 + lane] = o;
    }
}

// ---------------- layer2 attention coefficients: warp per node -------------
__global__ void k_alpha2(const float* __restrict__ a_src,
                         const float* __restrict__ a_dst) {
    int warp = (blockIdx.x * blockDim.x + threadIdx.x) >> 5;
    int lane = threadIdx.x & 31;
    if (warp >= NN) return;
    int n = warp;
    float h0 = g_h2[(size_t)n * H2S + lane];          // cols 0..31
    float s = h0 * a_src[lane];
    float d = h0 * a_dst[lane];
    if (lane < 8) {
        float h1v = g_h2[(size_t)n * H2S + 32 + lane]; // cols 32..39
        s += h1v * a_src[32 + lane];
        d += h1v * a_dst[32 + lane];
    }
#pragma unroll
    for (int off = 16; off > 0; off >>= 1) {
        s += __shfl_xor_sync(0xffffffffu, s, off);
        d += __shfl_xor_sync(0xffffffffu, d, off);
    }
    if (lane == 0) { g_as2[n] = s; g_ad2[n] = d; }
}

// ---------------- layer2 aggregate + bias + log_softmax: warp per node -----
__global__ void k_agg2(const float* __restrict__ b2, float* __restrict__ out) {
    int warp = (blockIdx.x * blockDim.x + threadIdx.x) >> 5;
    int lane = threadIdx.x & 31;
    if (warp >= NN) return;
    int n = warp;
    float adv = g_ad2[n];
    float acc0 = 0.f, acc1 = 0.f, ssum = 0.f;
    int start = g_rowstart[n];
    int cnt = g_cnt[n];
    for (int i = 0; i < cnt; i++) {
        int s = g_esrc[start + i];
        float e = g_as2[s] + adv;
        e = (e > 0.f) ? e : 0.2f * e;
        float w = expf(e);
        ssum += w;
        acc0 += w * g_h2[(size_t)s * H2S + lane];
        if (lane < 8) acc1 += w * g_h2[(size_t)s * H2S + 32 + lane];
    }
    float inv = 1.f / ssum;
    float v0 = acc0 * inv + b2[lane];
    float v1 = (lane < 8) ? (acc1 * inv + b2[32 + lane]) : -1e30f;
    // log_softmax over 40 values spread across (v0 all lanes, v1 lanes<8)
    float m = fmaxf(v0, v1);
#pragma unroll
    for (int off = 16; off > 0; off >>= 1)
        m = fmaxf(m, __shfl_xor_sync(0xffffffffu, m, off));
    float z = expf(v0 - m) + ((lane < 8) ? expf(v1 - m) : 0.f);
#pragma unroll
    for (int off = 16; off > 0; off >>= 1)
        z += __shfl_xor_sync(0xffffffffu, z, off);
    float lse = m + logf(z);
    out[(size_t)n * NOUT + lane] = v0 - lse;
    if (lane < 8) out[(size_t)n * NOUT + 32 + lane] = v1 - lse;
}

// ---------------- launcher ----------------
extern "C" void kernel_launch(void* const* d_in, const int* in_sizes, int n_in,
                              void* d_out, int out_size) {
    const float* x    = (const float*)d_in[0];
    const int*   ei32 = (const int*)d_in[1];   // int32 or int64 (sniffed on device)
    const float* W1   = (const float*)d_in[2];
    const float* as1p = (const float*)d_in[3];
    const float* ad1p = (const float*)d_in[4];
    const float* b1   = (const float*)d_in[5];
    const float* W2   = (const float*)d_in[6];
    const float* as2p = (const float*)d_in[7];
    const float* ad2p = (const float*)d_in[8];
    const float* b2   = (const float*)d_in[9];
    float*       out  = (float*)d_out;

    const int TPB = 256;
    int edgeBlocks = (ETOT + TPB - 1) / TPB;
    int warpBlocks = (NN * 32 + TPB - 1) / TPB;  // warp-per-node kernels

    k_detect<<<1, 1>>>(ei32);
    k_zero_cnt<<<(NN + TPB - 1) / TPB, TPB>>>();
    k_w2pad<<<(HCC * H2S) / TPB, TPB>>>(W2);

    // GEMM1: h1 = x @ W1   [50000,256]x[256,512]
    k_sgemm1<<<dim3(HCC / 64, (NN + 127) / 128), 256>>>(x, W1);

    k_alpha1<<<NN, 256>>>(as1p, ad1p);

    k_hist<<<edgeBlocks, TPB>>>(ei32);
    k_scan<<<1, 1024>>>();
    k_scatter<<<edgeBlocks, TPB>>>(ei32);

    k_agg1<<<warpBlocks, TPB>>>(b1);

    // GEMM2: h2 = agg1 @ W2pad   [50000,512]x[512,64]
    k_sgemm2<<<dim3(H2S / 64, (NN + 127) / 128), 256>>>();

    k_alpha2<<<warpBlocks, TPB>>>(as2p, ad2p);
    k_agg2<<<warpBlocks, TPB>>>(b2, out);
}

// round 5
// speedup vs baseline: 1.5202x; 1.5202x over previous
#include <cuda_runtime.h>
#include <math.h>

#define NN   50000
#define EE   800000
#define ETOT 850000
#define FIN  256
#define HCC  512      // H*C
#define NH   8
#define CHN  64
#define NOUT 40
#define H2S  64       // padded stride for layer-2 features

// ---------------- scratch (device globals; no allocation allowed) ----------
__device__ __align__(16) float g_h1[(size_t)NN * HCC];    // layer1 linear output
__device__ __align__(16) float g_agg1[(size_t)NN * HCC];  // layer1 GAT out (relu+bias)
__device__ __align__(16) float g_h2[(size_t)NN * H2S];    // layer2 linear (padded 64)
__device__ __align__(16) float g_W2p[HCC * H2S];
__device__ float g_as1[NN * NH];
__device__ float g_ad1[NN * NH];
__device__ float g_as2[NN];
__device__ float g_ad2[NN];
__device__ int   g_cnt[NN];
__device__ int   g_rowstart[NN];
__device__ int   g_cursor[NN];
__device__ int   g_esrc[ETOT];
__device__ int   g_e64;   // 1 if edge_index is int64, 0 if int32

// ---------------- edge dtype sniffing ----------------
// int64 values < 2^31 have zero odd 32-bit words; int32 edge ids are random.
__global__ void k_detect(const int* __restrict__ ei32) {
    int any = 0;
#pragma unroll
    for (int i = 1; i < 256; i += 2) any |= ei32[i];
    g_e64 = (any == 0) ? 1 : 0;
}

// ---------------- small utility kernels ----------------
__global__ void k_zero_cnt() {
    int i = blockIdx.x * blockDim.x + threadIdx.x;
    if (i < NN) g_cnt[i] = 0;
}

__global__ void k_w2pad(const float* __restrict__ W2) {
    int idx = blockIdx.x * blockDim.x + threadIdx.x;
    if (idx >= HCC * H2S) return;
    int r = idx >> 6, c = idx & 63;
    g_W2p[idx] = (c < NOUT) ? W2[r * NOUT + c] : 0.f;
}

// ============================================================================
// GEMM1: h1 = x @ W1, [50000,256]x[256,512], with fused alpha1 epilogue.
// BM=BN=128, BK=16, 256 threads, 8x8 per-thread tile, double-buffered smem.
// Each block's 128 columns = exactly 2 heads (64 ch each) -> alpha dots
// reduce fully in-block via 8-lane shuffle groups.
// ============================================================================
__global__ void __launch_bounds__(256, 2)
k_sgemm1(const float* __restrict__ A, const float* __restrict__ B,
         const float* __restrict__ a_src, const float* __restrict__ a_dst) {
    const int BK = 16;
    __shared__ __align__(16) float As[2][BK][128];
    __shared__ __align__(16) float Bs[2][BK][128];
    int tid = threadIdx.x;
    int ty = tid >> 4;          // 0..15
    int tx = tid & 15;          // 0..15
    int rowBase = blockIdx.y * 128;
    int colBase = blockIdx.x * 128;

    float4 pa[2], pb[2];

    // global loads for k-tile kt into registers
    auto gload = [&](int kt) {
#pragma unroll
        for (int it = 0; it < 2; it++) {
            int f = tid + it * 256;
            int r = f >> 2, k4 = f & 3;           // A: 512 float4 (128 rows x 4)
            int gr = rowBase + r;
            pa[it] = (gr < NN) ? *(const float4*)&A[(size_t)gr * FIN + kt + k4 * 4]
                               : make_float4(0.f, 0.f, 0.f, 0.f);
            int br = f >> 5, c4 = f & 31;         // B: 512 float4 (16 rows x 32)
            pb[it] = *(const float4*)&B[(size_t)(kt + br) * HCC + colBase + c4 * 4];
        }
    };
    auto sstore = [&](int buf) {
#pragma unroll
        for (int it = 0; it < 2; it++) {
            int f = tid + it * 256;
            int r = f >> 2, k4 = f & 3;
            As[buf][k4 * 4 + 0][r] = pa[it].x;
            As[buf][k4 * 4 + 1][r] = pa[it].y;
            As[buf][k4 * 4 + 2][r] = pa[it].z;
            As[buf][k4 * 4 + 3][r] = pa[it].w;
            int br = f >> 5, c4 = f & 31;
            *(float4*)&Bs[buf][br][c4 * 4] = pb[it];
        }
    };

    float acc[8][8];
#pragma unroll
    for (int i = 0; i < 8; i++)
#pragma unroll
        for (int j = 0; j < 8; j++) acc[i][j] = 0.f;

    gload(0);
    sstore(0);
    __syncthreads();
    int buf = 0;

    for (int kt = 0; kt < FIN; kt += BK) {
        bool hasNext = (kt + BK < FIN);
        if (hasNext) gload(kt + BK);
#pragma unroll
        for (int k = 0; k < BK; k++) {
            float ra[8], rb[8];
            *(float4*)&ra[0] = *(const float4*)&As[buf][k][ty * 8];
            *(float4*)&ra[4] = *(const float4*)&As[buf][k][ty * 8 + 4];
            *(float4*)&rb[0] = *(const float4*)&Bs[buf][k][tx * 8];
            *(float4*)&rb[4] = *(const float4*)&Bs[buf][k][tx * 8 + 4];
#pragma unroll
            for (int i = 0; i < 8; i++)
#pragma unroll
                for (int j = 0; j < 8; j++) acc[i][j] += ra[i] * rb[j];
        }
        if (hasNext) {
            sstore(buf ^ 1);
            __syncthreads();
            buf ^= 1;
        }
    }

    // ---- epilogue: write h1 + fused alpha1 partial dots ----
    float as_r[8], ad_r[8];
#pragma unroll
    for (int j = 0; j < 8; j++) {
        as_r[j] = a_src[colBase + tx * 8 + j];
        ad_r[j] = a_dst[colBase + tx * 8 + j];
    }
    int head = 2 * blockIdx.x + (tx >> 3);
    int lane = tid & 31;

#pragma unroll
    for (int i = 0; i < 8; i++) {
        int gr = rowBase + ty * 8 + i;
        float s = 0.f, d = 0.f;
#pragma unroll
        for (int j = 0; j < 8; j++) {
            s += acc[i][j] * as_r[j];
            d += acc[i][j] * ad_r[j];
        }
        // reduce over the 8 lanes covering this head's 64 channels
#pragma unroll
        for (int off = 4; off > 0; off >>= 1) {
            s += __shfl_xor_sync(0xffffffffu, s, off);
            d += __shfl_xor_sync(0xffffffffu, d, off);
        }
        if (gr < NN) {
            float4 o0 = make_float4(acc[i][0], acc[i][1], acc[i][2], acc[i][3]);
            float4 o1 = make_float4(acc[i][4], acc[i][5], acc[i][6], acc[i][7]);
            *(float4*)&g_h1[(size_t)gr * HCC + colBase + tx * 8]     = o0;
            *(float4*)&g_h1[(size_t)gr * HCC + colBase + tx * 8 + 4] = o1;
            if ((lane & 7) == 0) {
                g_as1[gr * NH + head] = s;
                g_ad1[gr * NH + head] = d;
            }
        }
    }
}

// ---------------- fp32 tiled SGEMM (layer 2): BM=128 BN=64 BK=16 ----------
__global__ void __launch_bounds__(256)
k_sgemm2() {
    const int BM = 128, BN = 64, BK = 16, TM = 8, TN = 4;
    const float* __restrict__ A = g_agg1;
    const float* __restrict__ B = g_W2p;
    float* __restrict__ C = g_h2;
    const int M = NN, K = HCC, Ncols = H2S;
    __shared__ __align__(16) float As[BK][BM];
    __shared__ __align__(16) float Bs[BK][BN];
    int tid = threadIdx.x;
    int rowBase = blockIdx.y * BM;
    int colBase = blockIdx.x * BN;
    int ty = tid / (BN / TN);
    int tx = tid % (BN / TN);

    float acc[TM][TN];
#pragma unroll
    for (int i = 0; i < TM; i++)
#pragma unroll
        for (int j = 0; j < TN; j++) acc[i][j] = 0.f;

    for (int kt = 0; kt < K; kt += BK) {
#pragma unroll
        for (int it = 0; it < 2; it++) {
            int f = tid + it * 256;
            int r = f >> 2;
            int k4 = f & 3;
            float4 v = make_float4(0.f, 0.f, 0.f, 0.f);
            int gr = rowBase + r;
            if (gr < M)
                v = *(const float4*)&A[(size_t)gr * K + kt + k4 * 4];
            As[k4 * 4 + 0][r] = v.x;
            As[k4 * 4 + 1][r] = v.y;
            As[k4 * 4 + 2][r] = v.z;
            As[k4 * 4 + 3][r] = v.w;
        }
        {
            int r = tid >> 4;
            int c4 = tid & 15;
            *(float4*)&Bs[r][c4 * 4] =
                *(const float4*)&B[(size_t)(kt + r) * Ncols + colBase + c4 * 4];
        }
        __syncthreads();
#pragma unroll
        for (int k = 0; k < BK; k++) {
            float ra[TM], rb[TN];
            float4 a0 = *(const float4*)&As[k][ty * TM];
            float4 a1 = *(const float4*)&As[k][ty * TM + 4];
            ra[0] = a0.x; ra[1] = a0.y; ra[2] = a0.z; ra[3] = a0.w;
            ra[4] = a1.x; ra[5] = a1.y; ra[6] = a1.z; ra[7] = a1.w;
            float4 b0 = *(const float4*)&Bs[k][tx * TN];
            rb[0] = b0.x; rb[1] = b0.y; rb[2] = b0.z; rb[3] = b0.w;
#pragma unroll
            for (int i = 0; i < TM; i++)
#pragma unroll
                for (int j = 0; j < TN; j++) acc[i][j] += ra[i] * rb[j];
        }
        __syncthreads();
    }
#pragma unroll
    for (int i = 0; i < TM; i++) {
        int gr = rowBase + ty * TM + i;
        if (gr < M) {
            float4 o = make_float4(acc[i][0], acc[i][1], acc[i][2], acc[i][3]);
            *(float4*)&C[(size_t)gr * Ncols + colBase + tx * TN] = o;
        }
    }
}

// ---------------- CSR build ----------------
__device__ __forceinline__ int edge_val(const int* __restrict__ ei32, int idx, int e64) {
    return e64 ? ei32[2 * (size_t)idx] : ei32[idx];
}

__global__ void k_hist(const int* __restrict__ ei32) {
    int e = blockIdx.x * blockDim.x + threadIdx.x;
    if (e >= ETOT) return;
    int e64 = g_e64;
    int dst = (e < EE) ? edge_val(ei32, EE + e, e64) : (e - EE);
    atomicAdd(&g_cnt[dst], 1);
}

__global__ void k_scan() {
    __shared__ int sh[1024];
    int t = threadIdx.x;
    const int CHUNK = 49;  // 1024*49 = 50176 >= 50000
    int lo = t * CHUNK;
    int hi = lo + CHUNK; if (hi > NN) hi = NN;
    int s = 0;
    for (int i = lo; i < hi; i++) s += g_cnt[i];
    sh[t] = s;
    __syncthreads();
    for (int off = 1; off < 1024; off <<= 1) {
        int v = (t >= off) ? sh[t - off] : 0;
        __syncthreads();
        sh[t] += v;
        __syncthreads();
    }
    int run = (t == 0) ? 0 : sh[t - 1];
    for (int i = lo; i < hi; i++) {
        g_rowstart[i] = run;
        g_cursor[i] = run;
        run += g_cnt[i];
    }
}

__global__ void k_scatter(const int* __restrict__ ei32) {
    int e = blockIdx.x * blockDim.x + threadIdx.x;
    if (e >= ETOT) return;
    int e64 = g_e64;
    int src, dst;
    if (e < EE) {
        src = edge_val(ei32, e, e64);
        dst = edge_val(ei32, EE + e, e64);
    } else {
        src = e - EE; dst = e - EE;
    }
    int p = atomicAdd(&g_cursor[dst], 1);
    g_esrc[p] = src;
}

// ---------------- layer1 aggregate: warp per dst node ----------------
// out[dst] = relu( sum_e softmax(e)*h1[src] + b1 )
// (max-shift skipped: logits are O(1), exp never overflows; math identical)
__global__ void k_agg1(const float* __restrict__ b1) {
    int warp = (blockIdx.x * blockDim.x + threadIdx.x) >> 5;
    int lane = threadIdx.x & 31;
    if (warp >= NN) return;
    int n = warp;
    float adv = 0.f;
    if (lane < NH) adv = g_ad1[n * NH + lane];
    float ssum = 0.f;
    float4 acc[4];
#pragma unroll
    for (int c = 0; c < 4; c++) acc[c] = make_float4(0.f, 0.f, 0.f, 0.f);

    int start = g_rowstart[n];
    int cnt = g_cnt[n];
    int hsel = lane >> 4;  // which half of the head-pair this lane's columns hit
    for (int i = 0; i < cnt; i++) {
        int s = g_esrc[start + i];
        float wv = 0.f;
        if (lane < NH) {
            float e = g_as1[s * NH + lane] + adv;
            e = (e > 0.f) ? e : 0.2f * e;
            wv = expf(e);
            ssum += wv;
        }
        const float4* hp = (const float4*)&g_h1[(size_t)s * HCC];
#pragma unroll
        for (int c = 0; c < 4; c++) {
            float w = __shfl_sync(0xffffffffu, wv, 2 * c + hsel);
            float4 hv = hp[c * 32 + lane];
            acc[c].x += w * hv.x;
            acc[c].y += w * hv.y;
            acc[c].z += w * hv.z;
            acc[c].w += w * hv.w;
        }
    }
    float4* op = (float4*)&g_agg1[(size_t)n * HCC];
#pragma unroll
    for (int c = 0; c < 4; c++) {
        float sden = __shfl_sync(0xffffffffu, ssum, 2 * c + hsel);
        float inv = 1.f / sden;
        float4 bv = *(const float4*)&b1[c * 128 + lane * 4];
        float4 o;
        o.x = fmaxf(acc[c].x * inv + bv.x, 0.f);
        o.y = fmaxf(acc[c].y * inv + bv.y, 0.f);
        o.z = fmaxf(acc[c].z * inv + bv.z, 0.f);
        o.w = fmaxf(acc[c].w * inv + bv.w, 0.f);
        op[c * 32 + lane] = o;
    }
}

// ---------------- layer2 attention coefficients: warp per node -------------
__global__ void k_alpha2(const float* __restrict__ a_src,
                         const float* __restrict__ a_dst) {
    int warp = (blockIdx.x * blockDim.x + threadIdx.x) >> 5;
    int lane = threadIdx.x & 31;
    if (warp >= NN) return;
    int n = warp;
    float h0 = g_h2[(size_t)n * H2S + lane];          // cols 0..31
    float s = h0 * a_src[lane];
    float d = h0 * a_dst[lane];
    if (lane < 8) {
        float h1v = g_h2[(size_t)n * H2S + 32 + lane]; // cols 32..39
        s += h1v * a_src[32 + lane];
        d += h1v * a_dst[32 + lane];
    }
#pragma unroll
    for (int off = 16; off > 0; off >>= 1) {
        s += __shfl_xor_sync(0xffffffffu, s, off);
        d += __shfl_xor_sync(0xffffffffu, d, off);
    }
    if (lane == 0) { g_as2[n] = s; g_ad2[n] = d; }
}

// ---------------- layer2 aggregate + bias + log_softmax: warp per node -----
__global__ void k_agg2(const float* __restrict__ b2, float* __restrict__ out) {
    int warp = (blockIdx.x * blockDim.x + threadIdx.x) >> 5;
    int lane = threadIdx.x & 31;
    if (warp >= NN) return;
    int n = warp;
    float adv = g_ad2[n];
    float acc0 = 0.f, acc1 = 0.f, ssum = 0.f;
    int start = g_rowstart[n];
    int cnt = g_cnt[n];
    for (int i = 0; i < cnt; i++) {
        int s = g_esrc[start + i];
        float e = g_as2[s] + adv;
        e = (e > 0.f) ? e : 0.2f * e;
        float w = expf(e);
        ssum += w;
        acc0 += w * g_h2[(size_t)s * H2S + lane];
        if (lane < 8) acc1 += w * g_h2[(size_t)s * H2S + 32 + lane];
    }
    float inv = 1.f / ssum;
    float v0 = acc0 * inv + b2[lane];
    float v1 = (lane < 8) ? (acc1 * inv + b2[32 + lane]) : -1e30f;
    // log_softmax over 40 values spread across (v0 all lanes, v1 lanes<8)
    float m = fmaxf(v0, v1);
#pragma unroll
    for (int off = 16; off > 0; off >>= 1)
        m = fmaxf(m, __shfl_xor_sync(0xffffffffu, m, off));
    float z = expf(v0 - m) + ((lane < 8) ? expf(v1 - m) : 0.f);
#pragma unroll
    for (int off = 16; off > 0; off >>= 1)
        z += __shfl_xor_sync(0xffffffffu, z, off);
    float lse = m + logf(z);
    out[(size_t)n * NOUT + lane] = v0 - lse;
    if (lane < 8) out[(size_t)n * NOUT + 32 + lane] = v1 - lse;
}

// ---------------- launcher ----------------
extern "C" void kernel_launch(void* const* d_in, const int* in_sizes, int n_in,
                              void* d_out, int out_size) {
    const float* x    = (const float*)d_in[0];
    const int*   ei32 = (const int*)d_in[1];   // int32 or int64 (sniffed on device)
    const float* W1   = (const float*)d_in[2];
    const float* as1p = (const float*)d_in[3];
    const float* ad1p = (const float*)d_in[4];
    const float* b1   = (const float*)d_in[5];
    const float* W2   = (const float*)d_in[6];
    const float* as2p = (const float*)d_in[7];
    const float* ad2p = (const float*)d_in[8];
    const float* b2   = (const float*)d_in[9];
    float*       out  = (float*)d_out;

    const int TPB = 256;
    int edgeBlocks = (ETOT + TPB - 1) / TPB;
    int warpBlocks = (NN * 32 + TPB - 1) / TPB;  // warp-per-node kernels

    k_detect<<<1, 1>>>(ei32);
    k_zero_cnt<<<(NN + TPB - 1) / TPB, TPB>>>();
    k_w2pad<<<(HCC * H2S) / TPB, TPB>>>(W2);

    // GEMM1 + fused alpha1: [50000,256]x[256,512]
    k_sgemm1<<<dim3(HCC / 128, (NN + 127) / 128), 256>>>(x, W1, as1p, ad1p);

    k_hist<<<edgeBlocks, TPB>>>(ei32);
    k_scan<<<1, 1024>>>();
    k_scatter<<<edgeBlocks, TPB>>>(ei32);

    k_agg1<<<warpBlocks, TPB>>>(b1);

    // GEMM2: h2 = agg1 @ W2pad   [50000,512]x[512,64]
    k_sgemm2<<<dim3(H2S / 64, (NN + 127) / 128), 256>>>();

    k_alpha2<<<warpBlocks, TPB>>>(as2p, ad2p);
    k_agg2<<<warpBlocks, TPB>>>(b2, out);
}

// round 7
// speedup vs baseline: 1.9500x; 1.2827x over previous
#include <cuda_runtime.h>
#include <cuda_bf16.h>
#include <math.h>
#include <stdint.h>

#define NN   50000
#define EE   800000
#define ETOT 850000
#define FIN  256
#define HCC  512      // H*C
#define NH   8
#define CHN  64
#define NOUT 40
#define H2S  64       // padded stride for layer-2 features

// ---------------- scratch (device globals; no allocation allowed) ----------
__device__ __align__(16) float g_h1[(size_t)NN * HCC];    // layer1 linear output
__device__ __align__(16) float g_agg1[(size_t)NN * HCC];  // layer1 GAT out (relu+bias)
__device__ __align__(16) float g_h2[(size_t)NN * H2S];    // layer2 linear (padded 64)
__device__ __align__(16) float g_W2p[HCC * H2S];
__device__ __align__(16) __nv_bfloat16 g_xhi[(size_t)NN * FIN];
__device__ __align__(16) __nv_bfloat16 g_xlo[(size_t)NN * FIN];
__device__ __align__(16) __nv_bfloat16 g_w1t_hi[HCC * FIN];   // [n][k] = W1[k][n]
__device__ __align__(16) __nv_bfloat16 g_w1t_lo[HCC * FIN];
__device__ float g_as1[NN * NH];
__device__ float g_ad1[NN * NH];
__device__ float g_as2[NN];
__device__ float g_ad2[NN];
__device__ int   g_cnt[NN];
__device__ int   g_rowstart[NN];
__device__ int   g_cursor[NN];
__device__ int   g_esrc[ETOT];
__device__ int   g_e64;   // 1 if edge_index is int64, 0 if int32

// ---------------- warp mma.sync bf16 (sm_80+, valid at compute_103) --------
__device__ __forceinline__ void mma16816(float* c, const uint32_t* a,
                                         const uint32_t* b) {
    asm volatile(
        "mma.sync.aligned.m16n8k16.row.col.f32.bf16.bf16.f32 "
        "{%0,%1,%2,%3}, {%4,%5,%6,%7}, {%8,%9}, {%0,%1,%2,%3};"
        : "+f"(c[0]), "+f"(c[1]), "+f"(c[2]), "+f"(c[3])
        : "r"(a[0]), "r"(a[1]), "r"(a[2]), "r"(a[3]), "r"(b[0]), "r"(b[1]));
}

// ---------------- edge dtype sniffing ----------------
__global__ void k_detect(const int* __restrict__ ei32) {
    int any = 0;
#pragma unroll
    for (int i = 1; i < 256; i += 2) any |= ei32[i];
    g_e64 = (any == 0) ? 1 : 0;
}

// ---------------- small utility kernels ----------------
__global__ void k_zero_cnt() {
    int i = blockIdx.x * blockDim.x + threadIdx.x;
    if (i < NN) g_cnt[i] = 0;
}

__global__ void k_w2pad(const float* __restrict__ W2) {
    int idx = blockIdx.x * blockDim.x + threadIdx.x;
    if (idx >= HCC * H2S) return;
    int r = idx >> 6, c = idx & 63;
    g_W2p[idx] = (c < NOUT) ? W2[r * NOUT + c] : 0.f;
}

// split fp32 -> bf16 hi + lo (4 elems/thread)
__global__ void k_conv_x(const float* __restrict__ x) {
    int i = blockIdx.x * blockDim.x + threadIdx.x;
    if (i >= (NN * FIN) / 4) return;
    float4 v = *(const float4*)&x[(size_t)i * 4];
    __nv_bfloat16 h0 = __float2bfloat16(v.x), h1 = __float2bfloat16(v.y);
    __nv_bfloat16 h2 = __float2bfloat16(v.z), h3 = __float2bfloat16(v.w);
    __nv_bfloat16 l0 = __float2bfloat16(v.x - __bfloat162float(h0));
    __nv_bfloat16 l1 = __float2bfloat16(v.y - __bfloat162float(h1));
    __nv_bfloat16 l2 = __float2bfloat16(v.z - __bfloat162float(h2));
    __nv_bfloat16 l3 = __float2bfloat16(v.w - __bfloat162float(h3));
    __nv_bfloat162* ph = (__nv_bfloat162*)&g_xhi[(size_t)i * 4];
    __nv_bfloat162* pl = (__nv_bfloat162*)&g_xlo[(size_t)i * 4];
    ph[0] = __nv_bfloat162(h0, h1); ph[1] = __nv_bfloat162(h2, h3);
    pl[0] = __nv_bfloat162(l0, l1); pl[1] = __nv_bfloat162(l2, l3);
}

// W1 [256,512] -> transposed bf16 hi/lo [512,256]
__global__ void k_conv_w1(const float* __restrict__ W1) {
    int idx = blockIdx.x * blockDim.x + threadIdx.x;
    if (idx >= HCC * FIN) return;
    int n = idx >> 8, k = idx & 255;
    float v = W1[(size_t)k * HCC + n];
    __nv_bfloat16 h = __float2bfloat16(v);
    g_w1t_hi[idx] = h;
    g_w1t_lo[idx] = __float2bfloat16(v - __bfloat162float(h));
}

// ============================================================================
// GEMM1: h1 = x @ W1 via split bf16 on mma.sync tensor cores, fused alpha1.
// Block 128x128, 8 warps (2x4), warp tile 64x32, K in 4 chunks of 64.
// Smem planes row-stride 72 bf16 (144B) -> conflict-free fragment loads.
// ============================================================================
#define STRB 144               // plane row stride in bytes (72 bf16)
#define OFF_AH 0
#define OFF_AL (128 * STRB)
#define OFF_BH (2 * 128 * STRB)
#define OFF_BL (3 * 128 * STRB)
#define OFF_AS (4 * 128 * STRB)            // 512B: a_src[128]
#define OFF_AD (OFF_AS + 512)              // 512B: a_dst[128]
#define OFF_RED (OFF_AD + 512)             // 128 rows x 4 floats = 2048B
#define SMEM1_TOTAL (OFF_RED + 2048)

__global__ void __launch_bounds__(256)
k_gemm1_mma(const float* __restrict__ a_src, const float* __restrict__ a_dst) {
    extern __shared__ __align__(16) char smem[];
    int tid = threadIdx.x;
    int wid = tid >> 5, lane = tid & 31;
    int wm = wid >> 2, wn = wid & 3;       // warp grid 2 (M) x 4 (N)
    int g = lane >> 2, t = lane & 3;
    int rowBase = blockIdx.y * 128;
    int colBase = blockIdx.x * 128;

    // preload alpha vectors + zero the reduction buffer
    if (tid < 128) ((float*)(smem + OFF_AS))[tid] = a_src[colBase + tid];
    else           ((float*)(smem + OFF_AD))[tid - 128] = a_dst[colBase + tid - 128];
    if (tid < 128) {
        float4 z = make_float4(0.f, 0.f, 0.f, 0.f);
        *(float4*)(smem + OFF_RED + tid * 16) = z;
    }

    float acc[4][4][4];
#pragma unroll
    for (int mt = 0; mt < 4; mt++)
#pragma unroll
        for (int nt = 0; nt < 4; nt++)
#pragma unroll
            for (int i = 0; i < 4; i++) acc[mt][nt][i] = 0.f;

    for (int ch = 0; ch < 4; ch++) {
        int kc = ch * 64;
        __syncthreads();
        // fill 4 planes: 128 rows x 64 bf16 each (8 uint4 per row)
#pragma unroll
        for (int it = 0; it < 4; it++) {
            int idx = tid + it * 256;          // 0..1023
            int r = idx >> 3, c16 = idx & 7;
            uint32_t so = (uint32_t)(r * STRB + c16 * 16);
            size_t ga = (size_t)(rowBase + r) * FIN + kc + c16 * 8;
            uint4 vh = make_uint4(0, 0, 0, 0), vl = make_uint4(0, 0, 0, 0);
            if (rowBase + r < NN) {
                vh = *(const uint4*)&g_xhi[ga];
                vl = *(const uint4*)&g_xlo[ga];
            }
            *(uint4*)(smem + OFF_AH + so) = vh;
            *(uint4*)(smem + OFF_AL + so) = vl;
            size_t gb = (size_t)(colBase + r) * FIN + kc + c16 * 8;
            *(uint4*)(smem + OFF_BH + so) = *(const uint4*)&g_w1t_hi[gb];
            *(uint4*)(smem + OFF_BL + so) = *(const uint4*)&g_w1t_lo[gb];
        }
        __syncthreads();
#pragma unroll
        for (int ks = 0; ks < 4; ks++) {
            int ko = ks * 16;
            uint32_t ah[4][4], al[4][4], bh[4][2], bl[4][2];
#pragma unroll
            for (int mt = 0; mt < 4; mt++) {
                int r0 = wm * 64 + mt * 16 + g;
                uint32_t o00 = (uint32_t)(r0 * STRB + (ko + 2 * t) * 2);
                uint32_t o10 = o00 + 8 * STRB;
                ah[mt][0] = *(const uint32_t*)(smem + OFF_AH + o00);
                ah[mt][1] = *(const uint32_t*)(smem + OFF_AH + o10);
                ah[mt][2] = *(const uint32_t*)(smem + OFF_AH + o00 + 16);
                ah[mt][3] = *(const uint32_t*)(smem + OFF_AH + o10 + 16);
                al[mt][0] = *(const uint32_t*)(smem + OFF_AL + o00);
                al[mt][1] = *(const uint32_t*)(smem + OFF_AL + o10);
                al[mt][2] = *(const uint32_t*)(smem + OFF_AL + o00 + 16);
                al[mt][3] = *(const uint32_t*)(smem + OFF_AL + o10 + 16);
            }
#pragma unroll
            for (int nt = 0; nt < 4; nt++) {
                int n = wn * 32 + nt * 8 + g;
                uint32_t o = (uint32_t)(n * STRB + (ko + 2 * t) * 2);
                bh[nt][0] = *(const uint32_t*)(smem + OFF_BH + o);
                bh[nt][1] = *(const uint32_t*)(smem + OFF_BH + o + 16);
                bl[nt][0] = *(const uint32_t*)(smem + OFF_BL + o);
                bl[nt][1] = *(const uint32_t*)(smem + OFF_BL + o + 16);
            }
#pragma unroll
            for (int mt = 0; mt < 4; mt++)
#pragma unroll
                for (int nt = 0; nt < 4; nt++) {
                    mma16816(acc[mt][nt], ah[mt], bh[nt]);
                    mma16816(acc[mt][nt], ah[mt], bl[nt]);
                    mma16816(acc[mt][nt], al[mt], bh[nt]);
                }
        }
    }
    __syncthreads();

    // ---- epilogue: write h1, fused alpha1 dots via smem reduction ----
    const float* as_s = (const float*)(smem + OFF_AS);
    const float* ad_s = (const float*)(smem + OFF_AD);
    float* red = (float*)(smem + OFF_RED);
    int hl = wn >> 1;   // which of the 2 heads in this 128-col block
#pragma unroll
    for (int mt = 0; mt < 4; mt++) {
        int r0 = wm * 64 + mt * 16 + g;
        int r1 = r0 + 8;
        int gr0 = rowBase + r0, gr1 = rowBase + r1;
        float s0 = 0.f, d0 = 0.f, s1 = 0.f, d1 = 0.f;
#pragma unroll
        for (int nt = 0; nt < 4; nt++) {
            int c = wn * 32 + nt * 8 + 2 * t;
            float* a = acc[mt][nt];
            if (gr0 < NN)
                *(float2*)&g_h1[(size_t)gr0 * HCC + colBase + c] =
                    make_float2(a[0], a[1]);
            if (gr1 < NN)
                *(float2*)&g_h1[(size_t)gr1 * HCC + colBase + c] =
                    make_float2(a[2], a[3]);
            float asv0 = as_s[c], asv1 = as_s[c + 1];
            float adv0 = ad_s[c], adv1 = ad_s[c + 1];
            s0 += a[0] * asv0 + a[1] * asv1;
            d0 += a[0] * adv0 + a[1] * adv1;
            s1 += a[2] * asv0 + a[3] * asv1;
            d1 += a[2] * adv0 + a[3] * adv1;
        }
#pragma unroll
        for (int off = 1; off <= 2; off <<= 1) {
            s0 += __shfl_xor_sync(0xffffffffu, s0, off);
            d0 += __shfl_xor_sync(0xffffffffu, d0, off);
            s1 += __shfl_xor_sync(0xffffffffu, s1, off);
            d1 += __shfl_xor_sync(0xffffffffu, d1, off);
        }
        if (t == 0) {
            atomicAdd(&red[r0 * 4 + hl * 2 + 0], s0);
            atomicAdd(&red[r0 * 4 + hl * 2 + 1], d0);
            atomicAdd(&red[r1 * 4 + hl * 2 + 0], s1);
            atomicAdd(&red[r1 * 4 + hl * 2 + 1], d1);
        }
    }
    __syncthreads();
    if (tid < 128) {
        int gr = rowBase + tid;
        if (gr < NN) {
            int h0 = 2 * blockIdx.x;
            g_as1[gr * NH + h0]     = red[tid * 4 + 0];
            g_ad1[gr * NH + h0]     = red[tid * 4 + 1];
            g_as1[gr * NH + h0 + 1] = red[tid * 4 + 2];
            g_ad1[gr * NH + h0 + 1] = red[tid * 4 + 3];
        }
    }
}

// ---------------- fp32 tiled SGEMM (layer 2): BM=128 BN=64 BK=16 ----------
__global__ void __launch_bounds__(256)
k_sgemm2() {
    const int BM = 128, BN = 64, BK = 16, TM = 8, TN = 4;
    const float* __restrict__ A = g_agg1;
    const float* __restrict__ B = g_W2p;
    float* __restrict__ C = g_h2;
    const int M = NN, K = HCC, Ncols = H2S;
    __shared__ __align__(16) float As[BK][BM];
    __shared__ __align__(16) float Bs[BK][BN];
    int tid = threadIdx.x;
    int rowBase = blockIdx.y * BM;
    int colBase = blockIdx.x * BN;
    int ty = tid / (BN / TN);
    int tx = tid % (BN / TN);

    float acc[TM][TN];
#pragma unroll
    for (int i = 0; i < TM; i++)
#pragma unroll
        for (int j = 0; j < TN; j++) acc[i][j] = 0.f;

    for (int kt = 0; kt < K; kt += BK) {
#pragma unroll
        for (int it = 0; it < 2; it++) {
            int f = tid + it * 256;
            int r = f >> 2;
            int k4 = f & 3;
            float4 v = make_float4(0.f, 0.f, 0.f, 0.f);
            int gr = rowBase + r;
            if (gr < M)
                v = *(const float4*)&A[(size_t)gr * K + kt + k4 * 4];
            As[k4 * 4 + 0][r] = v.x;
            As[k4 * 4 + 1][r] = v.y;
            As[k4 * 4 + 2][r] = v.z;
            As[k4 * 4 + 3][r] = v.w;
        }
        {
            int r = tid >> 4;
            int c4 = tid & 15;
            *(float4*)&Bs[r][c4 * 4] =
                *(const float4*)&B[(size_t)(kt + r) * Ncols + colBase + c4 * 4];
        }
        __syncthreads();
#pragma unroll
        for (int k = 0; k < BK; k++) {
            float ra[TM], rb[TN];
            float4 a0 = *(const float4*)&As[k][ty * TM];
            float4 a1 = *(const float4*)&As[k][ty * TM + 4];
            ra[0] = a0.x; ra[1] = a0.y; ra[2] = a0.z; ra[3] = a0.w;
            ra[4] = a1.x; ra[5] = a1.y; ra[6] = a1.z; ra[7] = a1.w;
            float4 b0 = *(const float4*)&Bs[k][tx * TN];
            rb[0] = b0.x; rb[1] = b0.y; rb[2] = b0.z; rb[3] = b0.w;
#pragma unroll
            for (int i = 0; i < TM; i++)
#pragma unroll
                for (int j = 0; j < TN; j++) acc[i][j] += ra[i] * rb[j];
        }
        __syncthreads();
    }
#pragma unroll
    for (int i = 0; i < TM; i++) {
        int gr = rowBase + ty * TM + i;
        if (gr < M) {
            float4 o = make_float4(acc[i][0], acc[i][1], acc[i][2], acc[i][3]);
            *(float4*)&C[(size_t)gr * Ncols + colBase + tx * TN] = o;
        }
    }
}

// ---------------- CSR build ----------------
__device__ __forceinline__ int edge_val(const int* __restrict__ ei32, int idx, int e64) {
    return e64 ? ei32[2 * (size_t)idx] : ei32[idx];
}

__global__ void k_hist(const int* __restrict__ ei32) {
    int e = blockIdx.x * blockDim.x + threadIdx.x;
    if (e >= ETOT) return;
    int e64 = g_e64;
    int dst = (e < EE) ? edge_val(ei32, EE + e, e64) : (e - EE);
    atomicAdd(&g_cnt[dst], 1);
}

__global__ void k_scan() {
    __shared__ int sh[1024];
    int t = threadIdx.x;
    const int CHUNK = 49;  // 1024*49 = 50176 >= 50000
    int lo = t * CHUNK;
    int hi = lo + CHUNK; if (hi > NN) hi = NN;
    int s = 0;
    for (int i = lo; i < hi; i++) s += g_cnt[i];
    sh[t] = s;
    __syncthreads();
    for (int off = 1; off < 1024; off <<= 1) {
        int v = (t >= off) ? sh[t - off] : 0;
        __syncthreads();
        sh[t] += v;
        __syncthreads();
    }
    int run = (t == 0) ? 0 : sh[t - 1];
    for (int i = lo; i < hi; i++) {
        g_rowstart[i] = run;
        g_cursor[i] = run;
        run += g_cnt[i];
    }
}

__global__ void k_scatter(const int* __restrict__ ei32) {
    int e = blockIdx.x * blockDim.x + threadIdx.x;
    if (e >= ETOT) return;
    int e64 = g_e64;
    int src, dst;
    if (e < EE) {
        src = edge_val(ei32, e, e64);
        dst = edge_val(ei32, EE + e, e64);
    } else {
        src = e - EE; dst = e - EE;
    }
    int p = atomicAdd(&g_cursor[dst], 1);
    g_esrc[p] = src;
}

// ---------------- layer1 aggregate: warp per dst node ----------------
__global__ void k_agg1(const float* __restrict__ b1) {
    int warp = (blockIdx.x * blockDim.x + threadIdx.x) >> 5;
    int lane = threadIdx.x & 31;
    if (warp >= NN) return;
    int n = warp;
    float adv = 0.f;
    if (lane < NH) adv = g_ad1[n * NH + lane];
    float ssum = 0.f;
    float4 acc[4];
#pragma unroll
    for (int c = 0; c < 4; c++) acc[c] = make_float4(0.f, 0.f, 0.f, 0.f);

    int start = g_rowstart[n];
    int cnt = g_cnt[n];
    int hsel = lane >> 4;
    for (int i = 0; i < cnt; i++) {
        int s = g_esrc[start + i];
        float wv = 0.f;
        if (lane < NH) {
            float e = g_as1[s * NH + lane] + adv;
            e = (e > 0.f) ? e : 0.2f * e;
            wv = expf(e);
            ssum += wv;
        }
        const float4* hp = (const float4*)&g_h1[(size_t)s * HCC];
#pragma unroll
        for (int c = 0; c < 4; c++) {
            float w = __shfl_sync(0xffffffffu, wv, 2 * c + hsel);
            float4 hv = hp[c * 32 + lane];
            acc[c].x += w * hv.x;
            acc[c].y += w * hv.y;
            acc[c].z += w * hv.z;
            acc[c].w += w * hv.w;
        }
    }
    float4* op = (float4*)&g_agg1[(size_t)n * HCC];
#pragma unroll
    for (int c = 0; c < 4; c++) {
        float sden = __shfl_sync(0xffffffffu, ssum, 2 * c + hsel);
        float inv = 1.f / sden;
        float4 bv = *(const float4*)&b1[c * 128 + lane * 4];
        float4 o;
        o.x = fmaxf(acc[c].x * inv + bv.x, 0.f);
        o.y = fmaxf(acc[c].y * inv + bv.y, 0.f);
        o.z = fmaxf(acc[c].z * inv + bv.z, 0.f);
        o.w = fmaxf(acc[c].w * inv + bv.w, 0.f);
        op[c * 32 + lane] = o;
    }
}

// ---------------- layer2 attention coefficients: warp per node -------------
__global__ void k_alpha2(const float* __restrict__ a_src,
                         const float* __restrict__ a_dst) {
    int warp = (blockIdx.x * blockDim.x + threadIdx.x) >> 5;
    int lane = threadIdx.x & 31;
    if (warp >= NN) return;
    int n = warp;
    float h0 = g_h2[(size_t)n * H2S + lane];
    float s = h0 * a_src[lane];
    float d = h0 * a_dst[lane];
    if (lane < 8) {
        float h1v = g_h2[(size_t)n * H2S + 32 + lane];
        s += h1v * a_src[32 + lane];
        d += h1v * a_dst[32 + lane];
    }
#pragma unroll
    for (int off = 16; off > 0; off >>= 1) {
        s += __shfl_xor_sync(0xffffffffu, s, off);
        d += __shfl_xor_sync(0xffffffffu, d, off);
    }
    if (lane == 0) { g_as2[n] = s; g_ad2[n] = d; }
}

// ---------------- layer2 aggregate + bias + log_softmax: warp per node -----
__global__ void k_agg2(const float* __restrict__ b2, float* __restrict__ out) {
    int warp = (blockIdx.x * blockDim.x + threadIdx.x) >> 5;
    int lane = threadIdx.x & 31;
    if (warp >= NN) return;
    int n = warp;
    float adv = g_ad2[n];
    float acc0 = 0.f, acc1 = 0.f, ssum = 0.f;
    int start = g_rowstart[n];
    int cnt = g_cnt[n];
    for (int i = 0; i < cnt; i++) {
        int s = g_esrc[start + i];
        float e = g_as2[s] + adv;
        e = (e > 0.f) ? e : 0.2f * e;
        float w = expf(e);
        ssum += w;
        acc0 += w * g_h2[(size_t)s * H2S + lane];
        if (lane < 8) acc1 += w * g_h2[(size_t)s * H2S + 32 + lane];
    }
    float inv = 1.f / ssum;
    float v0 = acc0 * inv + b2[lane];
    float v1 = (lane < 8) ? (acc1 * inv + b2[32 + lane]) : -1e30f;
    float m = fmaxf(v0, v1);
#pragma unroll
    for (int off = 16; off > 0; off >>= 1)
        m = fmaxf(m, __shfl_xor_sync(0xffffffffu, m, off));
    float z = expf(v0 - m) + ((lane < 8) ? expf(v1 - m) : 0.f);
#pragma unroll
    for (int off = 16; off > 0; off >>= 1)
        z += __shfl_xor_sync(0xffffffffu, z, off);
    float lse = m + logf(z);
    out[(size_t)n * NOUT + lane] = v0 - lse;
    if (lane < 8) out[(size_t)n * NOUT + 32 + lane] = v1 - lse;
}

// ---------------- launcher ----------------
extern "C" void kernel_launch(void* const* d_in, const int* in_sizes, int n_in,
                              void* d_out, int out_size) {
    const float* x    = (const float*)d_in[0];
    const int*   ei32 = (const int*)d_in[1];
    const float* W1   = (const float*)d_in[2];
    const float* as1p = (const float*)d_in[3];
    const float* ad1p = (const float*)d_in[4];
    const float* b1   = (const float*)d_in[5];
    const float* W2   = (const float*)d_in[6];
    const float* as2p = (const float*)d_in[7];
    const float* ad2p = (const float*)d_in[8];
    const float* b2   = (const float*)d_in[9];
    float*       out  = (float*)d_out;

    const int TPB = 256;
    int edgeBlocks = (ETOT + TPB - 1) / TPB;
    int warpBlocks = (NN * 32 + TPB - 1) / TPB;

    static int smem_set = 0;
    if (!smem_set) {
        cudaFuncSetAttribute(k_gemm1_mma,
                             cudaFuncAttributeMaxDynamicSharedMemorySize,
                             SMEM1_TOTAL);
        smem_set = 1;
    }

    k_detect<<<1, 1>>>(ei32);
    k_zero_cnt<<<(NN + TPB - 1) / TPB, TPB>>>();
    k_w2pad<<<(HCC * H2S) / TPB, TPB>>>(W2);
    k_conv_x<<<(NN * FIN / 4 + TPB - 1) / TPB, TPB>>>(x);
    k_conv_w1<<<(HCC * FIN + TPB - 1) / TPB, TPB>>>(W1);

    // GEMM1 (mma.sync split-bf16) + fused alpha1
    k_gemm1_mma<<<dim3(HCC / 128, (NN + 127) / 128), 256, SMEM1_TOTAL>>>(as1p, ad1p);

    k_hist<<<edgeBlocks, TPB>>>(ei32);
    k_scan<<<1, 1024>>>();
    k_scatter<<<edgeBlocks, TPB>>>(ei32);

    k_agg1<<<warpBlocks, TPB>>>(b1);

    // GEMM2: h2 = agg1 @ W2pad   [50000,512]x[512,64]
    k_sgemm2<<<dim3(H2S / 64, (NN + 127) / 128), 256>>>();

    k_alpha2<<<warpBlocks, TPB>>>(as2p, ad2p);
    k_agg2<<<warpBlocks, TPB>>>(b2, out);
}

// round 8
// speedup vs baseline: 2.4358x; 1.2492x over previous
#include <cuda_runtime.h>
#include <cuda_bf16.h>
#include <math.h>
#include <stdint.h>

#define NN   50000
#define EE   800000
#define ETOT 850000
#define FIN  256
#define HCC  512      // H*C
#define NH   8
#define CHN  64
#define NOUT 40
#define H2S  64       // padded layer-2 width

// ---------------- scratch (device globals; no allocation allowed) ----------
__device__ __align__(16) __nv_bfloat16 g_h1[(size_t)NN * HCC];     // layer1 linear out (bf16)
__device__ __align__(16) __nv_bfloat16 g_agg1h[(size_t)NN * HCC];  // layer1 GAT out hi
__device__ __align__(16) __nv_bfloat16 g_agg1l[(size_t)NN * HCC];  // layer1 GAT out lo
__device__ __align__(16) float g_h2[(size_t)NN * H2S];             // layer2 linear (fp32)
__device__ __align__(16) __nv_bfloat16 g_xhi[(size_t)NN * FIN];
__device__ __align__(16) __nv_bfloat16 g_xlo[(size_t)NN * FIN];
__device__ __align__(16) __nv_bfloat16 g_w1t_hi[HCC * FIN];   // [n][k] = W1[k][n]
__device__ __align__(16) __nv_bfloat16 g_w1t_lo[HCC * FIN];
__device__ __align__(16) __nv_bfloat16 g_w2t_hi[H2S * HCC];   // [n][k] = W2[k][n] (n>=40 zero)
__device__ __align__(16) __nv_bfloat16 g_w2t_lo[H2S * HCC];
__device__ float g_as1[NN * NH];
__device__ float g_ad1[NN * NH];
__device__ float g_as2[NN];
__device__ float g_ad2[NN];
__device__ int   g_cnt[NN];
__device__ int   g_rowstart[NN];
__device__ int   g_cursor[NN];
__device__ int   g_esrc[ETOT];
__device__ int   g_e64;   // 1 if edge_index is int64, 0 if int32

// ---------------- warp mma.sync bf16 (sm_80+, valid at compute_103) --------
__device__ __forceinline__ void mma16816(float* c, const uint32_t* a,
                                         const uint32_t* b) {
    asm volatile(
        "mma.sync.aligned.m16n8k16.row.col.f32.bf16.bf16.f32 "
        "{%0,%1,%2,%3}, {%4,%5,%6,%7}, {%8,%9}, {%0,%1,%2,%3};"
        : "+f"(c[0]), "+f"(c[1]), "+f"(c[2]), "+f"(c[3])
        : "r"(a[0]), "r"(a[1]), "r"(a[2]), "r"(a[3]), "r"(b[0]), "r"(b[1]));
}

__device__ __forceinline__ void fma_bf2(float& a0, float& a1, uint32_t p, float w) {
    __nv_bfloat162 b = *reinterpret_cast<__nv_bfloat162*>(&p);
    float2 f = __bfloat1622float2(b);
    a0 += w * f.x;
    a1 += w * f.y;
}

// ---------------- edge dtype sniffing ----------------
__global__ void k_detect(const int* __restrict__ ei32) {
    int any = 0;
#pragma unroll
    for (int i = 1; i < 256; i += 2) any |= ei32[i];
    g_e64 = (any == 0) ? 1 : 0;
}

__global__ void k_zero_cnt() {
    int i = blockIdx.x * blockDim.x + threadIdx.x;
    if (i < NN) g_cnt[i] = 0;
}

// split fp32 -> bf16 hi + lo (4 elems/thread)
__global__ void k_conv_x(const float* __restrict__ x) {
    int i = blockIdx.x * blockDim.x + threadIdx.x;
    if (i >= (NN * FIN) / 4) return;
    float4 v = *(const float4*)&x[(size_t)i * 4];
    __nv_bfloat16 h0 = __float2bfloat16(v.x), h1 = __float2bfloat16(v.y);
    __nv_bfloat16 h2 = __float2bfloat16(v.z), h3 = __float2bfloat16(v.w);
    __nv_bfloat16 l0 = __float2bfloat16(v.x - __bfloat162float(h0));
    __nv_bfloat16 l1 = __float2bfloat16(v.y - __bfloat162float(h1));
    __nv_bfloat16 l2 = __float2bfloat16(v.z - __bfloat162float(h2));
    __nv_bfloat16 l3 = __float2bfloat16(v.w - __bfloat162float(h3));
    __nv_bfloat162* ph = (__nv_bfloat162*)&g_xhi[(size_t)i * 4];
    __nv_bfloat162* pl = (__nv_bfloat162*)&g_xlo[(size_t)i * 4];
    ph[0] = __nv_bfloat162(h0, h1); ph[1] = __nv_bfloat162(h2, h3);
    pl[0] = __nv_bfloat162(l0, l1); pl[1] = __nv_bfloat162(l2, l3);
}

// W1 [256,512] -> transposed bf16 hi/lo [512,256]
__global__ void k_conv_w1(const float* __restrict__ W1) {
    int idx = blockIdx.x * blockDim.x + threadIdx.x;
    if (idx >= HCC * FIN) return;
    int n = idx >> 8, k = idx & 255;
    float v = W1[(size_t)k * HCC + n];
    __nv_bfloat16 h = __float2bfloat16(v);
    g_w1t_hi[idx] = h;
    g_w1t_lo[idx] = __float2bfloat16(v - __bfloat162float(h));
}

// W2 [512,40] -> transposed padded bf16 hi/lo [64,512]
__global__ void k_conv_w2(const float* __restrict__ W2) {
    int idx = blockIdx.x * blockDim.x + threadIdx.x;
    if (idx >= H2S * HCC) return;
    int n = idx >> 9, k = idx & 511;
    float v = (n < NOUT) ? W2[(size_t)k * NOUT + n] : 0.f;
    __nv_bfloat16 h = __float2bfloat16(v);
    g_w2t_hi[idx] = h;
    g_w2t_lo[idx] = __float2bfloat16(v - __bfloat162float(h));
}

// ============================================================================
// GEMM1: h1 = x @ W1 via split bf16 on mma.sync, fused alpha1, bf16 h1 out.
// Block 128x128, 8 warps (2x4), warp tile 64x32, K in 4 chunks of 64.
// ============================================================================
#define STRB 144               // plane row stride in bytes (72 bf16)
#define OFF_AH 0
#define OFF_AL (128 * STRB)
#define OFF_BH (2 * 128 * STRB)
#define OFF_BL (3 * 128 * STRB)
#define OFF_AS (4 * 128 * STRB)
#define OFF_AD (OFF_AS + 512)
#define OFF_RED (OFF_AD + 512)
#define SMEM1_TOTAL (OFF_RED + 2048)

__global__ void __launch_bounds__(256)
k_gemm1_mma(const float* __restrict__ a_src, const float* __restrict__ a_dst) {
    extern __shared__ __align__(16) char smem[];
    int tid = threadIdx.x;
    int wid = tid >> 5, lane = tid & 31;
    int wm = wid >> 2, wn = wid & 3;
    int g = lane >> 2, t = lane & 3;
    int rowBase = blockIdx.y * 128;
    int colBase = blockIdx.x * 128;

    if (tid < 128) ((float*)(smem + OFF_AS))[tid] = a_src[colBase + tid];
    else           ((float*)(smem + OFF_AD))[tid - 128] = a_dst[colBase + tid - 128];
    if (tid < 128) {
        float4 z = make_float4(0.f, 0.f, 0.f, 0.f);
        *(float4*)(smem + OFF_RED + tid * 16) = z;
    }

    float acc[4][4][4];
#pragma unroll
    for (int mt = 0; mt < 4; mt++)
#pragma unroll
        for (int nt = 0; nt < 4; nt++)
#pragma unroll
            for (int i = 0; i < 4; i++) acc[mt][nt][i] = 0.f;

    for (int ch = 0; ch < 4; ch++) {
        int kc = ch * 64;
        __syncthreads();
#pragma unroll
        for (int it = 0; it < 4; it++) {
            int idx = tid + it * 256;
            int r = idx >> 3, c16 = idx & 7;
            uint32_t so = (uint32_t)(r * STRB + c16 * 16);
            size_t ga = (size_t)(rowBase + r) * FIN + kc + c16 * 8;
            uint4 vh = make_uint4(0, 0, 0, 0), vl = make_uint4(0, 0, 0, 0);
            if (rowBase + r < NN) {
                vh = *(const uint4*)&g_xhi[ga];
                vl = *(const uint4*)&g_xlo[ga];
            }
            *(uint4*)(smem + OFF_AH + so) = vh;
            *(uint4*)(smem + OFF_AL + so) = vl;
            size_t gb = (size_t)(colBase + r) * FIN + kc + c16 * 8;
            *(uint4*)(smem + OFF_BH + so) = *(const uint4*)&g_w1t_hi[gb];
            *(uint4*)(smem + OFF_BL + so) = *(const uint4*)&g_w1t_lo[gb];
        }
        __syncthreads();
#pragma unroll
        for (int ks = 0; ks < 4; ks++) {
            int ko = ks * 16;
            uint32_t ah[4][4], al[4][4], bh[4][2], bl[4][2];
#pragma unroll
            for (int mt = 0; mt < 4; mt++) {
                int r0 = wm * 64 + mt * 16 + g;
                uint32_t o00 = (uint32_t)(r0 * STRB + (ko + 2 * t) * 2);
                uint32_t o10 = o00 + 8 * STRB;
                ah[mt][0] = *(const uint32_t*)(smem + OFF_AH + o00);
                ah[mt][1] = *(const uint32_t*)(smem + OFF_AH + o10);
                ah[mt][2] = *(const uint32_t*)(smem + OFF_AH + o00 + 16);
                ah[mt][3] = *(const uint32_t*)(smem + OFF_AH + o10 + 16);
                al[mt][0] = *(const uint32_t*)(smem + OFF_AL + o00);
                al[mt][1] = *(const uint32_t*)(smem + OFF_AL + o10);
                al[mt][2] = *(const uint32_t*)(smem + OFF_AL + o00 + 16);
                al[mt][3] = *(const uint32_t*)(smem + OFF_AL + o10 + 16);
            }
#pragma unroll
            for (int nt = 0; nt < 4; nt++) {
                int n = wn * 32 + nt * 8 + g;
                uint32_t o = (uint32_t)(n * STRB + (ko + 2 * t) * 2);
                bh[nt][0] = *(const uint32_t*)(smem + OFF_BH + o);
                bh[nt][1] = *(const uint32_t*)(smem + OFF_BH + o + 16);
                bl[nt][0] = *(const uint32_t*)(smem + OFF_BL + o);
                bl[nt][1] = *(const uint32_t*)(smem + OFF_BL + o + 16);
            }
#pragma unroll
            for (int mt = 0; mt < 4; mt++)
#pragma unroll
                for (int nt = 0; nt < 4; nt++) {
                    mma16816(acc[mt][nt], ah[mt], bh[nt]);
                    mma16816(acc[mt][nt], ah[mt], bl[nt]);
                    mma16816(acc[mt][nt], al[mt], bh[nt]);
                }
        }
    }
    __syncthreads();

    // ---- epilogue: write bf16 h1, fused alpha1 dots (fp32, exact) ----
    const float* as_s = (const float*)(smem + OFF_AS);
    const float* ad_s = (const float*)(smem + OFF_AD);
    float* red = (float*)(smem + OFF_RED);
    int hl = wn >> 1;
#pragma unroll
    for (int mt = 0; mt < 4; mt++) {
        int r0 = wm * 64 + mt * 16 + g;
        int r1 = r0 + 8;
        int gr0 = rowBase + r0, gr1 = rowBase + r1;
        float s0 = 0.f, d0 = 0.f, s1 = 0.f, d1 = 0.f;
#pragma unroll
        for (int nt = 0; nt < 4; nt++) {
            int c = wn * 32 + nt * 8 + 2 * t;
            float* a = acc[mt][nt];
            if (gr0 < NN)
                *(__nv_bfloat162*)&g_h1[(size_t)gr0 * HCC + colBase + c] =
                    __nv_bfloat162(__float2bfloat16(a[0]), __float2bfloat16(a[1]));
            if (gr1 < NN)
                *(__nv_bfloat162*)&g_h1[(size_t)gr1 * HCC + colBase + c] =
                    __nv_bfloat162(__float2bfloat16(a[2]), __float2bfloat16(a[3]));
            float asv0 = as_s[c], asv1 = as_s[c + 1];
            float adv0 = ad_s[c], adv1 = ad_s[c + 1];
            s0 += a[0] * asv0 + a[1] * asv1;
            d0 += a[0] * adv0 + a[1] * adv1;
            s1 += a[2] * asv0 + a[3] * asv1;
            d1 += a[2] * adv0 + a[3] * adv1;
        }
#pragma unroll
        for (int off = 1; off <= 2; off <<= 1) {
            s0 += __shfl_xor_sync(0xffffffffu, s0, off);
            d0 += __shfl_xor_sync(0xffffffffu, d0, off);
            s1 += __shfl_xor_sync(0xffffffffu, s1, off);
            d1 += __shfl_xor_sync(0xffffffffu, d1, off);
        }
        if (t == 0) {
            atomicAdd(&red[r0 * 4 + hl * 2 + 0], s0);
            atomicAdd(&red[r0 * 4 + hl * 2 + 1], d0);
            atomicAdd(&red[r1 * 4 + hl * 2 + 0], s1);
            atomicAdd(&red[r1 * 4 + hl * 2 + 1], d1);
        }
    }
    __syncthreads();
    if (tid < 128) {
        int gr = rowBase + tid;
        if (gr < NN) {
            int h0 = 2 * blockIdx.x;
            g_as1[gr * NH + h0]     = red[tid * 4 + 0];
            g_ad1[gr * NH + h0]     = red[tid * 4 + 1];
            g_as1[gr * NH + h0 + 1] = red[tid * 4 + 2];
            g_ad1[gr * NH + h0 + 1] = red[tid * 4 + 3];
        }
    }
}

// ============================================================================
// GEMM2: h2 = agg1 @ W2pad via split bf16 mma.sync, fused alpha2 epilogue.
// Block 128 rows x 64 cols, 8 warps (4x2), warp tile 32x32, K=512 in 8 chunks.
// ============================================================================
#define O2_AH 0
#define O2_AL (128 * STRB)
#define O2_BH (2 * 128 * STRB)
#define O2_BL (O2_BH + 64 * STRB)
#define O2_AS (O2_BH + 2 * 64 * STRB)
#define O2_AD (O2_AS + 256)
#define O2_RED (O2_AD + 256)
#define SMEM2_TOTAL (O2_RED + 1024)

__global__ void __launch_bounds__(256)
k_gemm2_mma(const float* __restrict__ a_src2, const float* __restrict__ a_dst2) {
    extern __shared__ __align__(16) char smem[];
    int tid = threadIdx.x;
    int wid = tid >> 5, lane = tid & 31;
    int wm = wid >> 1, wn = wid & 1;       // 4 (M) x 2 (N)
    int g = lane >> 2, t = lane & 3;
    int rowBase = blockIdx.x * 128;

    if (tid < 64)  ((float*)(smem + O2_AS))[tid] = (tid < NOUT) ? a_src2[tid] : 0.f;
    else if (tid < 128)
        ((float*)(smem + O2_AD))[tid - 64] = (tid - 64 < NOUT) ? a_dst2[tid - 64] : 0.f;
    if (tid < 128) *(float2*)(smem + O2_RED + tid * 8) = make_float2(0.f, 0.f);

    float acc[2][4][4];
#pragma unroll
    for (int mt = 0; mt < 2; mt++)
#pragma unroll
        for (int nt = 0; nt < 4; nt++)
#pragma unroll
            for (int i = 0; i < 4; i++) acc[mt][nt][i] = 0.f;

    for (int ch = 0; ch < 8; ch++) {
        int kc = ch * 64;
        __syncthreads();
#pragma unroll
        for (int it = 0; it < 4; it++) {                 // A: 128x64, hi+lo
            int idx = tid + it * 256;
            int r = idx >> 3, c8 = idx & 7;
            uint32_t so = (uint32_t)(r * STRB + c8 * 16);
            size_t ga = (size_t)(rowBase + r) * HCC + kc + c8 * 8;
            uint4 vh = make_uint4(0, 0, 0, 0), vl = make_uint4(0, 0, 0, 0);
            if (rowBase + r < NN) {
                vh = *(const uint4*)&g_agg1h[ga];
                vl = *(const uint4*)&g_agg1l[ga];
            }
            *(uint4*)(smem + O2_AH + so) = vh;
            *(uint4*)(smem + O2_AL + so) = vl;
        }
#pragma unroll
        for (int it = 0; it < 2; it++) {                 // B: 64x64, hi+lo
            int idx = tid + it * 256;
            int r = idx >> 3, c8 = idx & 7;
            uint32_t so = (uint32_t)(r * STRB + c8 * 16);
            size_t gb = (size_t)r * HCC + kc + c8 * 8;
            *(uint4*)(smem + O2_BH + so) = *(const uint4*)&g_w2t_hi[gb];
            *(uint4*)(smem + O2_BL + so) = *(const uint4*)&g_w2t_lo[gb];
        }
        __syncthreads();
#pragma unroll
        for (int ks = 0; ks < 4; ks++) {
            int ko = ks * 16;
            uint32_t ah[2][4], al[2][4], bh[4][2], bl[4][2];
#pragma unroll
            for (int mt = 0; mt < 2; mt++) {
                int r0 = wm * 32 + mt * 16 + g;
                uint32_t o00 = (uint32_t)(r0 * STRB + (ko + 2 * t) * 2);
                uint32_t o10 = o00 + 8 * STRB;
                ah[mt][0] = *(const uint32_t*)(smem + O2_AH + o00);
                ah[mt][1] = *(const uint32_t*)(smem + O2_AH + o10);
                ah[mt][2] = *(const uint32_t*)(smem + O2_AH + o00 + 16);
                ah[mt][3] = *(const uint32_t*)(smem + O2_AH + o10 + 16);
                al[mt][0] = *(const uint32_t*)(smem + O2_AL + o00);
                al[mt][1] = *(const uint32_t*)(smem + O2_AL + o10);
                al[mt][2] = *(const uint32_t*)(smem + O2_AL + o00 + 16);
                al[mt][3] = *(const uint32_t*)(smem + O2_AL + o10 + 16);
            }
#pragma unroll
            for (int nt = 0; nt < 4; nt++) {
                int n = wn * 32 + nt * 8 + g;
                uint32_t o = (uint32_t)(n * STRB + (ko + 2 * t) * 2);
                bh[nt][0] = *(const uint32_t*)(smem + O2_BH + o);
                bh[nt][1] = *(const uint32_t*)(smem + O2_BH + o + 16);
                bl[nt][0] = *(const uint32_t*)(smem + O2_BL + o);
                bl[nt][1] = *(const uint32_t*)(smem + O2_BL + o + 16);
            }
#pragma unroll
            for (int mt = 0; mt < 2; mt++)
#pragma unroll
                for (int nt = 0; nt < 4; nt++) {
                    mma16816(acc[mt][nt], ah[mt], bh[nt]);
                    mma16816(acc[mt][nt], ah[mt], bl[nt]);
                    mma16816(acc[mt][nt], al[mt], bh[nt]);
                }
        }
    }
    __syncthreads();

    // ---- epilogue: write h2 fp32, fused alpha2 dots ----
    const float* as_s = (const float*)(smem + O2_AS);
    const float* ad_s = (const float*)(smem + O2_AD);
    float* red = (float*)(smem + O2_RED);
#pragma unroll
    for (int mt = 0; mt < 2; mt++) {
        int r0 = wm * 32 + mt * 16 + g;
        int r1 = r0 + 8;
        int gr0 = rowBase + r0, gr1 = rowBase + r1;
        float s0 = 0.f, d0 = 0.f, s1 = 0.f, d1 = 0.f;
#pragma unroll
        for (int nt = 0; nt < 4; nt++) {
            int c = wn * 32 + nt * 8 + 2 * t;
            float* a = acc[mt][nt];
            if (gr0 < NN)
                *(float2*)&g_h2[(size_t)gr0 * H2S + c] = make_float2(a[0], a[1]);
            if (gr1 < NN)
                *(float2*)&g_h2[(size_t)gr1 * H2S + c] = make_float2(a[2], a[3]);
            float asv0 = as_s[c], asv1 = as_s[c + 1];
            float adv0 = ad_s[c], adv1 = ad_s[c + 1];
            s0 += a[0] * asv0 + a[1] * asv1;
            d0 += a[0] * adv0 + a[1] * adv1;
            s1 += a[2] * asv0 + a[3] * asv1;
            d1 += a[2] * adv0 + a[3] * adv1;
        }
#pragma unroll
        for (int off = 1; off <= 2; off <<= 1) {
            s0 += __shfl_xor_sync(0xffffffffu, s0, off);
            d0 += __shfl_xor_sync(0xffffffffu, d0, off);
            s1 += __shfl_xor_sync(0xffffffffu, s1, off);
            d1 += __shfl_xor_sync(0xffffffffu, d1, off);
        }
        if (t == 0) {
            atomicAdd(&red[r0 * 2 + 0], s0);
            atomicAdd(&red[r0 * 2 + 1], d0);
            atomicAdd(&red[r1 * 2 + 0], s1);
            atomicAdd(&red[r1 * 2 + 1], d1);
        }
    }
    __syncthreads();
    if (tid < 128) {
        int gr = rowBase + tid;
        if (gr < NN) {
            g_as2[gr] = red[tid * 2 + 0];
            g_ad2[gr] = red[tid * 2 + 1];
        }
    }
}

// ---------------- CSR build ----------------
__device__ __forceinline__ int edge_val(const int* __restrict__ ei32, int idx, int e64) {
    return e64 ? ei32[2 * (size_t)idx] : ei32[idx];
}

__global__ void k_hist(const int* __restrict__ ei32) {
    int e = blockIdx.x * blockDim.x + threadIdx.x;
    if (e >= ETOT) return;
    int e64 = g_e64;
    int dst = (e < EE) ? edge_val(ei32, EE + e, e64) : (e - EE);
    atomicAdd(&g_cnt[dst], 1);
}

__global__ void k_scan() {
    __shared__ int sh[1024];
    int t = threadIdx.x;
    const int CHUNK = 49;
    int lo = t * CHUNK;
    int hi = lo + CHUNK; if (hi > NN) hi = NN;
    int s = 0;
    for (int i = lo; i < hi; i++) s += g_cnt[i];
    sh[t] = s;
    __syncthreads();
    for (int off = 1; off < 1024; off <<= 1) {
        int v = (t >= off) ? sh[t - off] : 0;
        __syncthreads();
        sh[t] += v;
        __syncthreads();
    }
    int run = (t == 0) ? 0 : sh[t - 1];
    for (int i = lo; i < hi; i++) {
        g_rowstart[i] = run;
        g_cursor[i] = run;
        run += g_cnt[i];
    }
}

__global__ void k_scatter(const int* __restrict__ ei32) {
    int e = blockIdx.x * blockDim.x + threadIdx.x;
    if (e >= ETOT) return;
    int e64 = g_e64;
    int src, dst;
    if (e < EE) {
        src = edge_val(ei32, e, e64);
        dst = edge_val(ei32, EE + e, e64);
    } else {
        src = e - EE; dst = e - EE;
    }
    int p = atomicAdd(&g_cursor[dst], 1);
    g_esrc[p] = src;
}

// ---------------- layer1 aggregate: warp per dst node (bf16 h1) ------------
// out[dst] = relu( (sum_e exp(e)*h1[src]) / sum_e exp(e) + b1 ), hi/lo split
__global__ void k_agg1(const float* __restrict__ b1) {
    int warp = (blockIdx.x * blockDim.x + threadIdx.x) >> 5;
    int lane = threadIdx.x & 31;
    if (warp >= NN) return;
    int n = warp;
    float adv = 0.f;
    if (lane < NH) adv = g_ad1[n * NH + lane];
    float ssum = 0.f;
    float acc[16];
#pragma unroll
    for (int j = 0; j < 16; j++) acc[j] = 0.f;

    int start = g_rowstart[n];
    int cnt = g_cnt[n];
    int hsel = lane >> 2;          // head covering this lane's 16 channels
    for (int i = 0; i < cnt; i++) {
        int s = g_esrc[start + i];
        float wv = 0.f;
        if (lane < NH) {
            float e = g_as1[s * NH + lane] + adv;
            e = (e > 0.f) ? e : 0.2f * e;
            wv = expf(e);
            ssum += wv;
        }
        float w = __shfl_sync(0xffffffffu, wv, hsel);
        const __nv_bfloat16* hp = &g_h1[(size_t)s * HCC + lane * 16];
        uint4 v0 = *(const uint4*)hp;
        uint4 v1 = *(const uint4*)(hp + 8);
        fma_bf2(acc[0],  acc[1],  v0.x, w);
        fma_bf2(acc[2],  acc[3],  v0.y, w);
        fma_bf2(acc[4],  acc[5],  v0.z, w);
        fma_bf2(acc[6],  acc[7],  v0.w, w);
        fma_bf2(acc[8],  acc[9],  v1.x, w);
        fma_bf2(acc[10], acc[11], v1.y, w);
        fma_bf2(acc[12], acc[13], v1.z, w);
        fma_bf2(acc[14], acc[15], v1.w, w);
    }
    float sden = __shfl_sync(0xffffffffu, ssum, hsel);
    float inv = 1.f / sden;
    __nv_bfloat16 hi[16], lo[16];
#pragma unroll
    for (int j = 0; j < 16; j++) {
        float o = fmaxf(acc[j] * inv + b1[lane * 16 + j], 0.f);
        __nv_bfloat16 h = __float2bfloat16(o);
        hi[j] = h;
        lo[j] = __float2bfloat16(o - __bfloat162float(h));
    }
    __nv_bfloat16* oph = &g_agg1h[(size_t)n * HCC + lane * 16];
    __nv_bfloat16* opl = &g_agg1l[(size_t)n * HCC + lane * 16];
    *(uint4*)oph       = *(uint4*)&hi[0];
    *(uint4*)(oph + 8) = *(uint4*)&hi[8];
    *(uint4*)opl       = *(uint4*)&lo[0];
    *(uint4*)(opl + 8) = *(uint4*)&lo[8];
}

// ---------------- layer2 aggregate + bias + log_softmax: warp per node -----
__global__ void k_agg2(const float* __restrict__ b2, float* __restrict__ out) {
    int warp = (blockIdx.x * blockDim.x + threadIdx.x) >> 5;
    int lane = threadIdx.x & 31;
    if (warp >= NN) return;
    int n = warp;
    float adv = g_ad2[n];
    float acc0 = 0.f, acc1 = 0.f, ssum = 0.f;
    int start = g_rowstart[n];
    int cnt = g_cnt[n];
    for (int i = 0; i < cnt; i++) {
        int s = g_esrc[start + i];
        float e = g_as2[s] + adv;
        e = (e > 0.f) ? e : 0.2f * e;
        float w = expf(e);
        ssum += w;
        acc0 += w * g_h2[(size_t)s * H2S + lane];
        if (lane < 8) acc1 += w * g_h2[(size_t)s * H2S + 32 + lane];
    }
    float inv = 1.f / ssum;
    float v0 = acc0 * inv + b2[lane];
    float v1 = (lane < 8) ? (acc1 * inv + b2[32 + lane]) : -1e30f;
    float m = fmaxf(v0, v1);
#pragma unroll
    for (int off = 16; off > 0; off >>= 1)
        m = fmaxf(m, __shfl_xor_sync(0xffffffffu, m, off));
    float z = expf(v0 - m) + ((lane < 8) ? expf(v1 - m) : 0.f);
#pragma unroll
    for (int off = 16; off > 0; off >>= 1)
        z += __shfl_xor_sync(0xffffffffu, z, off);
    float lse = m + logf(z);
    out[(size_t)n * NOUT + lane] = v0 - lse;
    if (lane < 8) out[(size_t)n * NOUT + 32 + lane] = v1 - lse;
}

// ---------------- launcher ----------------
extern "C" void kernel_launch(void* const* d_in, const int* in_sizes, int n_in,
                              void* d_out, int out_size) {
    const float* x    = (const float*)d_in[0];
    const int*   ei32 = (const int*)d_in[1];
    const float* W1   = (const float*)d_in[2];
    const float* as1p = (const float*)d_in[3];
    const float* ad1p = (const float*)d_in[4];
    const float* b1   = (const float*)d_in[5];
    const float* W2   = (const float*)d_in[6];
    const float* as2p = (const float*)d_in[7];
    const float* ad2p = (const float*)d_in[8];
    const float* b2   = (const float*)d_in[9];
    float*       out  = (float*)d_out;

    const int TPB = 256;
    int edgeBlocks = (ETOT + TPB - 1) / TPB;
    int warpBlocks = (NN * 32 + TPB - 1) / TPB;

    static int smem_set = 0;
    if (!smem_set) {
        cudaFuncSetAttribute(k_gemm1_mma,
                             cudaFuncAttributeMaxDynamicSharedMemorySize,
                             SMEM1_TOTAL);
        cudaFuncSetAttribute(k_gemm2_mma,
                             cudaFuncAttributeMaxDynamicSharedMemorySize,
                             SMEM2_TOTAL);
        smem_set = 1;
    }

    k_detect<<<1, 1>>>(ei32);
    k_zero_cnt<<<(NN + TPB - 1) / TPB, TPB>>>();
    k_conv_x<<<(NN * FIN / 4 + TPB - 1) / TPB, TPB>>>(x);
    k_conv_w1<<<(HCC * FIN + TPB - 1) / TPB, TPB>>>(W1);
    k_conv_w2<<<(H2S * HCC + TPB - 1) / TPB, TPB>>>(W2);

    // GEMM1 (mma.sync split-bf16) + fused alpha1
    k_gemm1_mma<<<dim3(HCC / 128, (NN + 127) / 128), 256, SMEM1_TOTAL>>>(as1p, ad1p);

    k_hist<<<edgeBlocks, TPB>>>(ei32);
    k_scan<<<1, 1024>>>();
    k_scatter<<<edgeBlocks, TPB>>>(ei32);

    k_agg1<<<warpBlocks, TPB>>>(b1);

    // GEMM2 (mma.sync split-bf16) + fused alpha2
    k_gemm2_mma<<<(NN + 127) / 128, 256, SMEM2_TOTAL>>>(as2p, ad2p);

    k_agg2<<<warpBlocks, TPB>>>(b2, out);
}

// round 9
// speedup vs baseline: 3.0051x; 1.2337x over previous
#include <cuda_runtime.h>
#include <cuda_bf16.h>
#include <math.h>
#include <stdint.h>

#define NN   50000
#define EE   800000
#define ETOT 850000
#define FIN  256
#define HCC  512      // H*C
#define NH   8
#define CHN  64
#define NOUT 40
#define H2S  64       // padded layer-2 width

// ---------------- scratch (device globals; no allocation allowed) ----------
__device__ __align__(16) __nv_bfloat16 g_h1[(size_t)NN * HCC];     // layer1 linear out (bf16)
__device__ __align__(16) __nv_bfloat16 g_agg1h[(size_t)NN * HCC];  // layer1 GAT out hi
__device__ __align__(16) __nv_bfloat16 g_agg1l[(size_t)NN * HCC];  // layer1 GAT out lo
__device__ __align__(16) __nv_bfloat16 g_h2b[(size_t)NN * H2S];    // layer2 linear (bf16)
__device__ __align__(16) __nv_bfloat16 g_xhi[(size_t)NN * FIN];
__device__ __align__(16) __nv_bfloat16 g_xlo[(size_t)NN * FIN];
__device__ __align__(16) __nv_bfloat16 g_w1t_hi[HCC * FIN];   // [n][k] = W1[k][n]
__device__ __align__(16) __nv_bfloat16 g_w1t_lo[HCC * FIN];
__device__ __align__(16) __nv_bfloat16 g_w2t_hi[H2S * HCC];   // [n][k] = W2[k][n] (n>=40 zero)
__device__ __align__(16) __nv_bfloat16 g_w2t_lo[H2S * HCC];
__device__ float g_as1[NN * NH];
__device__ float g_ad1[NN * NH];
__device__ float g_as2[NN];
__device__ float g_ad2[NN];
__device__ int   g_cnt[NN];
__device__ int   g_rowstart[NN];
__device__ int   g_cursor[NN];
__device__ int   g_esrc[ETOT];
__device__ int   g_e64;   // 1 if edge_index is int64, 0 if int32

// ---------------- warp mma.sync bf16 (sm_80+, valid at compute_103) --------
__device__ __forceinline__ void mma16816(float* c, const uint32_t* a,
                                         const uint32_t* b) {
    asm volatile(
        "mma.sync.aligned.m16n8k16.row.col.f32.bf16.bf16.f32 "
        "{%0,%1,%2,%3}, {%4,%5,%6,%7}, {%8,%9}, {%0,%1,%2,%3};"
        : "+f"(c[0]), "+f"(c[1]), "+f"(c[2]), "+f"(c[3])
        : "r"(a[0]), "r"(a[1]), "r"(a[2]), "r"(a[3]), "r"(b[0]), "r"(b[1]));
}

__device__ __forceinline__ void fma_bf2(float& a0, float& a1, uint32_t p, float w) {
    __nv_bfloat162 b = *reinterpret_cast<__nv_bfloat162*>(&p);
    float2 f = __bfloat1622float2(b);
    a0 += w * f.x;
    a1 += w * f.y;
}

// ---------------- init: zero counts + edge dtype sniff ----------------
// int64 values < 2^31 have zero odd 32-bit words; int32 edge ids are random.
__global__ void k_init(const int* __restrict__ ei32) {
    int i = blockIdx.x * blockDim.x + threadIdx.x;
    if (i < NN) g_cnt[i] = 0;
    if (i == 0) {
        int any = 0;
#pragma unroll
        for (int j = 1; j < 256; j += 2) any |= ei32[j];
        g_e64 = (any == 0) ? 1 : 0;
    }
}

// split fp32 -> bf16 hi + lo (4 elems/thread)
__global__ void k_conv_x(const float* __restrict__ x) {
    int i = blockIdx.x * blockDim.x + threadIdx.x;
    if (i >= (NN * FIN) / 4) return;
    float4 v = *(const float4*)&x[(size_t)i * 4];
    __nv_bfloat16 h0 = __float2bfloat16(v.x), h1 = __float2bfloat16(v.y);
    __nv_bfloat16 h2 = __float2bfloat16(v.z), h3 = __float2bfloat16(v.w);
    __nv_bfloat16 l0 = __float2bfloat16(v.x - __bfloat162float(h0));
    __nv_bfloat16 l1 = __float2bfloat16(v.y - __bfloat162float(h1));
    __nv_bfloat16 l2 = __float2bfloat16(v.z - __bfloat162float(h2));
    __nv_bfloat16 l3 = __float2bfloat16(v.w - __bfloat162float(h3));
    __nv_bfloat162* ph = (__nv_bfloat162*)&g_xhi[(size_t)i * 4];
    __nv_bfloat162* pl = (__nv_bfloat162*)&g_xlo[(size_t)i * 4];
    ph[0] = __nv_bfloat162(h0, h1); ph[1] = __nv_bfloat162(h2, h3);
    pl[0] = __nv_bfloat162(l0, l1); pl[1] = __nv_bfloat162(l2, l3);
}

// W1 [256,512] -> transposed bf16 hi/lo [512,256]
__global__ void k_conv_w1(const float* __restrict__ W1) {
    int idx = blockIdx.x * blockDim.x + threadIdx.x;
    if (idx >= HCC * FIN) return;
    int n = idx >> 8, k = idx & 255;
    float v = W1[(size_t)k * HCC + n];
    __nv_bfloat16 h = __float2bfloat16(v);
    g_w1t_hi[idx] = h;
    g_w1t_lo[idx] = __float2bfloat16(v - __bfloat162float(h));
}

// W2 [512,40] -> transposed padded bf16 hi/lo [64,512]
__global__ void k_conv_w2(const float* __restrict__ W2) {
    int idx = blockIdx.x * blockDim.x + threadIdx.x;
    if (idx >= H2S * HCC) return;
    int n = idx >> 9, k = idx & 511;
    float v = (n < NOUT) ? W2[(size_t)k * NOUT + n] : 0.f;
    __nv_bfloat16 h = __float2bfloat16(v);
    g_w2t_hi[idx] = h;
    g_w2t_lo[idx] = __float2bfloat16(v - __bfloat162float(h));
}

// ============================================================================
// GEMM1: h1 = x @ W1 via split bf16 on mma.sync, fused alpha1, bf16 h1 out.
// Block 128x128, 8 warps (2x4), warp tile 64x32, K in 4 chunks of 64.
// ============================================================================
#define STRB 144               // plane row stride in bytes (72 bf16)
#define OFF_AH 0
#define OFF_AL (128 * STRB)
#define OFF_BH (2 * 128 * STRB)
#define OFF_BL (3 * 128 * STRB)
#define OFF_AS (4 * 128 * STRB)
#define OFF_AD (OFF_AS + 512)
#define OFF_RED (OFF_AD + 512)
#define SMEM1_TOTAL (OFF_RED + 2048)

__global__ void __launch_bounds__(256)
k_gemm1_mma(const float* __restrict__ a_src, const float* __restrict__ a_dst) {
    extern __shared__ __align__(16) char smem[];
    int tid = threadIdx.x;
    int wid = tid >> 5, lane = tid & 31;
    int wm = wid >> 2, wn = wid & 3;
    int g = lane >> 2, t = lane & 3;
    int rowBase = blockIdx.y * 128;
    int colBase = blockIdx.x * 128;

    if (tid < 128) ((float*)(smem + OFF_AS))[tid] = a_src[colBase + tid];
    else           ((float*)(smem + OFF_AD))[tid - 128] = a_dst[colBase + tid - 128];
    if (tid < 128) {
        float4 z = make_float4(0.f, 0.f, 0.f, 0.f);
        *(float4*)(smem + OFF_RED + tid * 16) = z;
    }

    float acc[4][4][4];
#pragma unroll
    for (int mt = 0; mt < 4; mt++)
#pragma unroll
        for (int nt = 0; nt < 4; nt++)
#pragma unroll
            for (int i = 0; i < 4; i++) acc[mt][nt][i] = 0.f;

    for (int ch = 0; ch < 4; ch++) {
        int kc = ch * 64;
        __syncthreads();
#pragma unroll
        for (int it = 0; it < 4; it++) {
            int idx = tid + it * 256;
            int r = idx >> 3, c16 = idx & 7;
            uint32_t so = (uint32_t)(r * STRB + c16 * 16);
            size_t ga = (size_t)(rowBase + r) * FIN + kc + c16 * 8;
            uint4 vh = make_uint4(0, 0, 0, 0), vl = make_uint4(0, 0, 0, 0);
            if (rowBase + r < NN) {
                vh = *(const uint4*)&g_xhi[ga];
                vl = *(const uint4*)&g_xlo[ga];
            }
            *(uint4*)(smem + OFF_AH + so) = vh;
            *(uint4*)(smem + OFF_AL + so) = vl;
            size_t gb = (size_t)(colBase + r) * FIN + kc + c16 * 8;
            *(uint4*)(smem + OFF_BH + so) = *(const uint4*)&g_w1t_hi[gb];
            *(uint4*)(smem + OFF_BL + so) = *(const uint4*)&g_w1t_lo[gb];
        }
        __syncthreads();
#pragma unroll
        for (int ks = 0; ks < 4; ks++) {
            int ko = ks * 16;
            uint32_t ah[4][4], al[4][4], bh[4][2], bl[4][2];
#pragma unroll
            for (int mt = 0; mt < 4; mt++) {
                int r0 = wm * 64 + mt * 16 + g;
                uint32_t o00 = (uint32_t)(r0 * STRB + (ko + 2 * t) * 2);
                uint32_t o10 = o00 + 8 * STRB;
                ah[mt][0] = *(const uint32_t*)(smem + OFF_AH + o00);
                ah[mt][1] = *(const uint32_t*)(smem + OFF_AH + o10);
                ah[mt][2] = *(const uint32_t*)(smem + OFF_AH + o00 + 16);
                ah[mt][3] = *(const uint32_t*)(smem + OFF_AH + o10 + 16);
                al[mt][0] = *(const uint32_t*)(smem + OFF_AL + o00);
                al[mt][1] = *(const uint32_t*)(smem + OFF_AL + o10);
                al[mt][2] = *(const uint32_t*)(smem + OFF_AL + o00 + 16);
                al[mt][3] = *(const uint32_t*)(smem + OFF_AL + o10 + 16);
            }
#pragma unroll
            for (int nt = 0; nt < 4; nt++) {
                int n = wn * 32 + nt * 8 + g;
                uint32_t o = (uint32_t)(n * STRB + (ko + 2 * t) * 2);
                bh[nt][0] = *(const uint32_t*)(smem + OFF_BH + o);
                bh[nt][1] = *(const uint32_t*)(smem + OFF_BH + o + 16);
                bl[nt][0] = *(const uint32_t*)(smem + OFF_BL + o);
                bl[nt][1] = *(const uint32_t*)(smem + OFF_BL + o + 16);
            }
#pragma unroll
            for (int mt = 0; mt < 4; mt++)
#pragma unroll
                for (int nt = 0; nt < 4; nt++) {
                    mma16816(acc[mt][nt], ah[mt], bh[nt]);
                    mma16816(acc[mt][nt], ah[mt], bl[nt]);
                    mma16816(acc[mt][nt], al[mt], bh[nt]);
                }
        }
    }
    __syncthreads();

    // ---- epilogue: write bf16 h1, fused alpha1 dots (fp32, exact) ----
    const float* as_s = (const float*)(smem + OFF_AS);
    const float* ad_s = (const float*)(smem + OFF_AD);
    float* red = (float*)(smem + OFF_RED);
    int hl = wn >> 1;
#pragma unroll
    for (int mt = 0; mt < 4; mt++) {
        int r0 = wm * 64 + mt * 16 + g;
        int r1 = r0 + 8;
        int gr0 = rowBase + r0, gr1 = rowBase + r1;
        float s0 = 0.f, d0 = 0.f, s1 = 0.f, d1 = 0.f;
#pragma unroll
        for (int nt = 0; nt < 4; nt++) {
            int c = wn * 32 + nt * 8 + 2 * t;
            float* a = acc[mt][nt];
            if (gr0 < NN)
                *(__nv_bfloat162*)&g_h1[(size_t)gr0 * HCC + colBase + c] =
                    __nv_bfloat162(__float2bfloat16(a[0]), __float2bfloat16(a[1]));
            if (gr1 < NN)
                *(__nv_bfloat162*)&g_h1[(size_t)gr1 * HCC + colBase + c] =
                    __nv_bfloat162(__float2bfloat16(a[2]), __float2bfloat16(a[3]));
            float asv0 = as_s[c], asv1 = as_s[c + 1];
            float adv0 = ad_s[c], adv1 = ad_s[c + 1];
            s0 += a[0] * asv0 + a[1] * asv1;
            d0 += a[0] * adv0 + a[1] * adv1;
            s1 += a[2] * asv0 + a[3] * asv1;
            d1 += a[2] * adv0 + a[3] * adv1;
        }
#pragma unroll
        for (int off = 1; off <= 2; off <<= 1) {
            s0 += __shfl_xor_sync(0xffffffffu, s0, off);
            d0 += __shfl_xor_sync(0xffffffffu, d0, off);
            s1 += __shfl_xor_sync(0xffffffffu, s1, off);
            d1 += __shfl_xor_sync(0xffffffffu, d1, off);
        }
        if (t == 0) {
            atomicAdd(&red[r0 * 4 + hl * 2 + 0], s0);
            atomicAdd(&red[r0 * 4 + hl * 2 + 1], d0);
            atomicAdd(&red[r1 * 4 + hl * 2 + 0], s1);
            atomicAdd(&red[r1 * 4 + hl * 2 + 1], d1);
        }
    }
    __syncthreads();
    if (tid < 128) {
        int gr = rowBase + tid;
        if (gr < NN) {
            int h0 = 2 * blockIdx.x;
            g_as1[gr * NH + h0]     = red[tid * 4 + 0];
            g_ad1[gr * NH + h0]     = red[tid * 4 + 1];
            g_as1[gr * NH + h0 + 1] = red[tid * 4 + 2];
            g_ad1[gr * NH + h0 + 1] = red[tid * 4 + 3];
        }
    }
}

// ============================================================================
// GEMM2: h2 = agg1 @ W2pad via split bf16 mma.sync, fused alpha2 epilogue.
// Block 128 rows x 64 cols, 8 warps (4x2), warp tile 32x32, K=512 in 8 chunks.
// ============================================================================
#define O2_AH 0
#define O2_AL (128 * STRB)
#define O2_BH (2 * 128 * STRB)
#define O2_BL (O2_BH + 64 * STRB)
#define O2_AS (O2_BH + 2 * 64 * STRB)
#define O2_AD (O2_AS + 256)
#define O2_RED (O2_AD + 256)
#define SMEM2_TOTAL (O2_RED + 1024)

__global__ void __launch_bounds__(256)
k_gemm2_mma(const float* __restrict__ a_src2, const float* __restrict__ a_dst2) {
    extern __shared__ __align__(16) char smem[];
    int tid = threadIdx.x;
    int wid = tid >> 5, lane = tid & 31;
    int wm = wid >> 1, wn = wid & 1;       // 4 (M) x 2 (N)
    int g = lane >> 2, t = lane & 3;
    int rowBase = blockIdx.x * 128;

    if (tid < 64)  ((float*)(smem + O2_AS))[tid] = (tid < NOUT) ? a_src2[tid] : 0.f;
    else if (tid < 128)
        ((float*)(smem + O2_AD))[tid - 64] = (tid - 64 < NOUT) ? a_dst2[tid - 64] : 0.f;
    if (tid < 128) *(float2*)(smem + O2_RED + tid * 8) = make_float2(0.f, 0.f);

    float acc[2][4][4];
#pragma unroll
    for (int mt = 0; mt < 2; mt++)
#pragma unroll
        for (int nt = 0; nt < 4; nt++)
#pragma unroll
            for (int i = 0; i < 4; i++) acc[mt][nt][i] = 0.f;

    for (int ch = 0; ch < 8; ch++) {
        int kc = ch * 64;
        __syncthreads();
#pragma unroll
        for (int it = 0; it < 4; it++) {                 // A: 128x64, hi+lo
            int idx = tid + it * 256;
            int r = idx >> 3, c8 = idx & 7;
            uint32_t so = (uint32_t)(r * STRB + c8 * 16);
            size_t ga = (size_t)(rowBase + r) * HCC + kc + c8 * 8;
            uint4 vh = make_uint4(0, 0, 0, 0), vl = make_uint4(0, 0, 0, 0);
            if (rowBase + r < NN) {
                vh = *(const uint4*)&g_agg1h[ga];
                vl = *(const uint4*)&g_agg1l[ga];
            }
            *(uint4*)(smem + O2_AH + so) = vh;
            *(uint4*)(smem + O2_AL + so) = vl;
        }
#pragma unroll
        for (int it = 0; it < 2; it++) {                 // B: 64x64, hi+lo
            int idx = tid + it * 256;
            int r = idx >> 3, c8 = idx & 7;
            uint32_t so = (uint32_t)(r * STRB + c8 * 16);
            size_t gb = (size_t)r * HCC + kc + c8 * 8;
            *(uint4*)(smem + O2_BH + so) = *(const uint4*)&g_w2t_hi[gb];
            *(uint4*)(smem + O2_BL + so) = *(const uint4*)&g_w2t_lo[gb];
        }
        __syncthreads();
#pragma unroll
        for (int ks = 0; ks < 4; ks++) {
            int ko = ks * 16;
            uint32_t ah[2][4], al[2][4], bh[4][2], bl[4][2];
#pragma unroll
            for (int mt = 0; mt < 2; mt++) {
                int r0 = wm * 32 + mt * 16 + g;
                uint32_t o00 = (uint32_t)(r0 * STRB + (ko + 2 * t) * 2);
                uint32_t o10 = o00 + 8 * STRB;
                ah[mt][0] = *(const uint32_t*)(smem + O2_AH + o00);
                ah[mt][1] = *(const uint32_t*)(smem + O2_AH + o10);
                ah[mt][2] = *(const uint32_t*)(smem + O2_AH + o00 + 16);
                ah[mt][3] = *(const uint32_t*)(smem + O2_AH + o10 + 16);
                al[mt][0] = *(const uint32_t*)(smem + O2_AL + o00);
                al[mt][1] = *(const uint32_t*)(smem + O2_AL + o10);
                al[mt][2] = *(const uint32_t*)(smem + O2_AL + o00 + 16);
                al[mt][3] = *(const uint32_t*)(smem + O2_AL + o10 + 16);
            }
#pragma unroll
            for (int nt = 0; nt < 4; nt++) {
                int n = wn * 32 + nt * 8 + g;
                uint32_t o = (uint32_t)(n * STRB + (ko + 2 * t) * 2);
                bh[nt][0] = *(const uint32_t*)(smem + O2_BH + o);
                bh[nt][1] = *(const uint32_t*)(smem + O2_BH + o + 16);
                bl[nt][0] = *(const uint32_t*)(smem + O2_BL + o);
                bl[nt][1] = *(const uint32_t*)(smem + O2_BL + o + 16);
            }
#pragma unroll
            for (int mt = 0; mt < 2; mt++)
#pragma unroll
                for (int nt = 0; nt < 4; nt++) {
                    mma16816(acc[mt][nt], ah[mt], bh[nt]);
                    mma16816(acc[mt][nt], ah[mt], bl[nt]);
                    mma16816(acc[mt][nt], al[mt], bh[nt]);
                }
        }
    }
    __syncthreads();

    // ---- epilogue: write h2 bf16, fused alpha2 dots (fp32, exact) ----
    const float* as_s = (const float*)(smem + O2_AS);
    const float* ad_s = (const float*)(smem + O2_AD);
    float* red = (float*)(smem + O2_RED);
#pragma unroll
    for (int mt = 0; mt < 2; mt++) {
        int r0 = wm * 32 + mt * 16 + g;
        int r1 = r0 + 8;
        int gr0 = rowBase + r0, gr1 = rowBase + r1;
        float s0 = 0.f, d0 = 0.f, s1 = 0.f, d1 = 0.f;
#pragma unroll
        for (int nt = 0; nt < 4; nt++) {
            int c = wn * 32 + nt * 8 + 2 * t;
            float* a = acc[mt][nt];
            if (gr0 < NN)
                *(__nv_bfloat162*)&g_h2b[(size_t)gr0 * H2S + c] =
                    __nv_bfloat162(__float2bfloat16(a[0]), __float2bfloat16(a[1]));
            if (gr1 < NN)
                *(__nv_bfloat162*)&g_h2b[(size_t)gr1 * H2S + c] =
                    __nv_bfloat162(__float2bfloat16(a[2]), __float2bfloat16(a[3]));
            float asv0 = as_s[c], asv1 = as_s[c + 1];
            float adv0 = ad_s[c], adv1 = ad_s[c + 1];
            s0 += a[0] * asv0 + a[1] * asv1;
            d0 += a[0] * adv0 + a[1] * adv1;
            s1 += a[2] * asv0 + a[3] * asv1;
            d1 += a[2] * adv0 + a[3] * adv1;
        }
#pragma unroll
        for (int off = 1; off <= 2; off <<= 1) {
            s0 += __shfl_xor_sync(0xffffffffu, s0, off);
            d0 += __shfl_xor_sync(0xffffffffu, d0, off);
            s1 += __shfl_xor_sync(0xffffffffu, s1, off);
            d1 += __shfl_xor_sync(0xffffffffu, d1, off);
        }
        if (t == 0) {
            atomicAdd(&red[r0 * 2 + 0], s0);
            atomicAdd(&red[r0 * 2 + 1], d0);
            atomicAdd(&red[r1 * 2 + 0], s1);
            atomicAdd(&red[r1 * 2 + 1], d1);
        }
    }
    __syncthreads();
    if (tid < 128) {
        int gr = rowBase + tid;
        if (gr < NN) {
            g_as2[gr] = red[tid * 2 + 0];
            g_ad2[gr] = red[tid * 2 + 1];
        }
    }
}

// ---------------- CSR build ----------------
__device__ __forceinline__ int edge_val(const int* __restrict__ ei32, int idx, int e64) {
    return e64 ? ei32[2 * (size_t)idx] : ei32[idx];
}

__global__ void k_hist(const int* __restrict__ ei32) {
    int e = blockIdx.x * blockDim.x + threadIdx.x;
    if (e >= ETOT) return;
    int e64 = g_e64;
    int dst = (e < EE) ? edge_val(ei32, EE + e, e64) : (e - EE);
    atomicAdd(&g_cnt[dst], 1);
}

__global__ void k_scan() {
    __shared__ int sh[1024];
    int t = threadIdx.x;
    const int CHUNK = 49;
    int lo = t * CHUNK;
    int hi = lo + CHUNK; if (hi > NN) hi = NN;
    int s = 0;
    for (int i = lo; i < hi; i++) s += g_cnt[i];
    sh[t] = s;
    __syncthreads();
    for (int off = 1; off < 1024; off <<= 1) {
        int v = (t >= off) ? sh[t - off] : 0;
        __syncthreads();
        sh[t] += v;
        __syncthreads();
    }
    int run = (t == 0) ? 0 : sh[t - 1];
    for (int i = lo; i < hi; i++) {
        g_rowstart[i] = run;
        g_cursor[i] = run;
        run += g_cnt[i];
    }
}

__global__ void k_scatter(const int* __restrict__ ei32) {
    int e = blockIdx.x * blockDim.x + threadIdx.x;
    if (e >= ETOT) return;
    int e64 = g_e64;
    int src, dst;
    if (e < EE) {
        src = edge_val(ei32, e, e64);
        dst = edge_val(ei32, EE + e, e64);
    } else {
        src = e - EE; dst = e - EE;
    }
    int p = atomicAdd(&g_cursor[dst], 1);
    g_esrc[p] = src;
}

// ---------------- layer1 aggregate: warp per dst node (bf16 h1) ------------
__global__ void k_agg1(const float* __restrict__ b1) {
    int warp = (blockIdx.x * blockDim.x + threadIdx.x) >> 5;
    int lane = threadIdx.x & 31;
    if (warp >= NN) return;
    int n = warp;
    float adv = 0.f;
    if (lane < NH) adv = g_ad1[n * NH + lane];
    float ssum = 0.f;
    float acc[16];
#pragma unroll
    for (int j = 0; j < 16; j++) acc[j] = 0.f;

    int start = g_rowstart[n];
    int cnt = g_cnt[n];
    int hsel = lane >> 2;          // head covering this lane's 16 channels
    for (int i = 0; i < cnt; i++) {
        int s = g_esrc[start + i];
        float wv = 0.f;
        if (lane < NH) {
            float e = g_as1[s * NH + lane] + adv;
            e = (e > 0.f) ? e : 0.2f * e;
            wv = expf(e);
            ssum += wv;
        }
        float w = __shfl_sync(0xffffffffu, wv, hsel);
        const __nv_bfloat16* hp = &g_h1[(size_t)s * HCC + lane * 16];
        uint4 v0 = *(const uint4*)hp;
        uint4 v1 = *(const uint4*)(hp + 8);
        fma_bf2(acc[0],  acc[1],  v0.x, w);
        fma_bf2(acc[2],  acc[3],  v0.y, w);
        fma_bf2(acc[4],  acc[5],  v0.z, w);
        fma_bf2(acc[6],  acc[7],  v0.w, w);
        fma_bf2(acc[8],  acc[9],  v1.x, w);
        fma_bf2(acc[10], acc[11], v1.y, w);
        fma_bf2(acc[12], acc[13], v1.z, w);
        fma_bf2(acc[14], acc[15], v1.w, w);
    }
    float sden = __shfl_sync(0xffffffffu, ssum, hsel);
    float inv = 1.f / sden;
    __nv_bfloat16 hi[16], lo[16];
#pragma unroll
    for (int j = 0; j < 16; j++) {
        float o = fmaxf(acc[j] * inv + b1[lane * 16 + j], 0.f);
        __nv_bfloat16 h = __float2bfloat16(o);
        hi[j] = h;
        lo[j] = __float2bfloat16(o - __bfloat162float(h));
    }
    __nv_bfloat16* oph = &g_agg1h[(size_t)n * HCC + lane * 16];
    __nv_bfloat16* opl = &g_agg1l[(size_t)n * HCC + lane * 16];
    *(uint4*)oph       = *(uint4*)&hi[0];
    *(uint4*)(oph + 8) = *(uint4*)&hi[8];
    *(uint4*)opl       = *(uint4*)&lo[0];
    *(uint4*)(opl + 8) = *(uint4*)&lo[8];
}

// ---------------- layer2 aggregate + bias + log_softmax: warp per node -----
// h2 is bf16; lane j owns channels (2j, 2j+1); channels >= 40 are invalid.
__global__ void k_agg2(const float* __restrict__ b2, float* __restrict__ out) {
    int warp = (blockIdx.x * blockDim.x + threadIdx.x) >> 5;
    int lane = threadIdx.x & 31;
    if (warp >= NN) return;
    int n = warp;
    float adv = g_ad2[n];
    float a0 = 0.f, a1 = 0.f, ssum = 0.f;
    int start = g_rowstart[n];
    int cnt = g_cnt[n];
    const uint32_t* h2u = (const uint32_t*)g_h2b;
    for (int i = 0; i < cnt; i++) {
        int s = g_esrc[start + i];
        float e = g_as2[s] + adv;
        e = (e > 0.f) ? e : 0.2f * e;
        float w = expf(e);
        ssum += w;
        uint32_t p = h2u[(size_t)s * (H2S / 2) + lane];
        fma_bf2(a0, a1, p, w);
    }
    float inv = 1.f / ssum;
    bool valid = (lane < NOUT / 2);   // lanes 0..19 own two valid channels
    float v0 = -1e30f, v1 = -1e30f;
    if (valid) {
        v0 = a0 * inv + b2[2 * lane];
        v1 = a1 * inv + b2[2 * lane + 1];
    }
    float m = fmaxf(v0, v1);
#pragma unroll
    for (int off = 16; off > 0; off >>= 1)
        m = fmaxf(m, __shfl_xor_sync(0xffffffffu, m, off));
    float z = valid ? (expf(v0 - m) + expf(v1 - m)) : 0.f;
#pragma unroll
    for (int off = 16; off > 0; off >>= 1)
        z += __shfl_xor_sync(0xffffffffu, z, off);
    float lse = m + logf(z);
    if (valid)
        *(float2*)&out[(size_t)n * NOUT + 2 * lane] = make_float2(v0 - lse, v1 - lse);
}

// ---------------- launcher ----------------
extern "C" void kernel_launch(void* const* d_in, const int* in_sizes, int n_in,
                              void* d_out, int out_size) {
    const float* x    = (const float*)d_in[0];
    const int*   ei32 = (const int*)d_in[1];
    const float* W1   = (const float*)d_in[2];
    const float* as1p = (const float*)d_in[3];
    const float* ad1p = (const float*)d_in[4];
    const float* b1   = (const float*)d_in[5];
    const float* W2   = (const float*)d_in[6];
    const float* as2p = (const float*)d_in[7];
    const float* ad2p = (const float*)d_in[8];
    const float* b2   = (const float*)d_in[9];
    float*       out  = (float*)d_out;

    const int TPB = 256;
    int edgeBlocks = (ETOT + TPB - 1) / TPB;
    int warpBlocks = (NN * 32 + TPB - 1) / TPB;

    static cudaStream_t s1 = nullptr;
    static cudaEvent_t ev0 = nullptr, ev1 = nullptr;
    if (!s1) {
        cudaFuncSetAttribute(k_gemm1_mma,
                             cudaFuncAttributeMaxDynamicSharedMemorySize,
                             SMEM1_TOTAL);
        cudaFuncSetAttribute(k_gemm2_mma,
                             cudaFuncAttributeMaxDynamicSharedMemorySize,
                             SMEM2_TOTAL);
        cudaStreamCreateWithFlags(&s1, cudaStreamNonBlocking);
        cudaEventCreateWithFlags(&ev0, cudaEventDisableTiming);
        cudaEventCreateWithFlags(&ev1, cudaEventDisableTiming);
    }

    // -- fork: CSR build on s1, conv + GEMM1 on the main stream --
    k_init<<<(NN + TPB - 1) / TPB, TPB>>>(ei32);
    cudaEventRecord(ev0, 0);
    cudaStreamWaitEvent(s1, ev0, 0);

    k_hist<<<edgeBlocks, TPB, 0, s1>>>(ei32);
    k_scan<<<1, 1024, 0, s1>>>();
    k_scatter<<<edgeBlocks, TPB, 0, s1>>>(ei32);
    cudaEventRecord(ev1, s1);

    k_conv_x<<<(NN * FIN / 4 + TPB - 1) / TPB, TPB>>>(x);
    k_conv_w1<<<(HCC * FIN + TPB - 1) / TPB, TPB>>>(W1);
    k_conv_w2<<<(H2S * HCC + TPB - 1) / TPB, TPB>>>(W2);
    k_gemm1_mma<<<dim3(HCC / 128, (NN + 127) / 128), 256, SMEM1_TOTAL>>>(as1p, ad1p);

    cudaStreamWaitEvent(0, ev1, 0);   // join before aggregation

    k_agg1<<<warpBlocks, TPB>>>(b1);
    k_gemm2_mma<<<(NN + 127) / 128, 256, SMEM2_TOTAL>>>(as2p, ad2p);
    k_agg2<<<warpBlocks, TPB>>>(b2, out);
}